// round 1
// baseline (speedup 1.0000x reference)
#include <cuda_runtime.h>
#include <math.h>
#include <stdint.h>

// Problem constants
#define Bc    2
#define Tc    2048
#define Cc    2048
#define NHc   32
#define NGc   8
#define QPKc  4
#define HSc   64
#define QKVD  3072          // (32 + 2*8) * 64
#define BTc   (Bc*Tc)       // 4096

// Scratch (device globals: allocation-free)
__device__ float g_qkv[(size_t)BTc * QKVD];                    // 50.3 MB
__device__ float g_q[(size_t)Bc * NGc * QPKc * Tc * HSc];      // 33.5 MB
__device__ float g_k[(size_t)Bc * NGc * Tc * HSc];             // 8.4 MB
__device__ float g_v[(size_t)Bc * NGc * Tc * HSc];             // 8.4 MB
__device__ float g_y[(size_t)BTc * Cc];                        // 33.5 MB

// ---------------------------------------------------------------------------
// GEMM (NT): C[M,N] = A[M,K] @ W[N,K]^T + bias[N]
// 128x128 block tile, BK=8, 256 threads, 8x8 per thread, 1-stage prefetch.
// ---------------------------------------------------------------------------
__global__ __launch_bounds__(256) void gemm_nt(
    const float* __restrict__ A, const float* __restrict__ W,
    const float* __restrict__ bias, float* __restrict__ Cm,
    int M, int N, int K)
{
    __shared__ float As[8][128];
    __shared__ float Bs[8][128];

    const int tid = threadIdx.x;
    const int tx = tid & 15;        // 0..15
    const int ty = tid >> 4;        // 0..15
    const int m0 = blockIdx.y << 7;
    const int n0 = blockIdx.x << 7;

    const int lrow = tid >> 1;          // 0..127
    const int lk   = (tid & 1) << 2;    // 0 or 4

    const float* Ap = A + (size_t)(m0 + lrow) * K + lk;
    const float* Wp = W + (size_t)(n0 + lrow) * K + lk;

    float4 av = *(const float4*)Ap;
    float4 wv = *(const float4*)Wp;

    float acc[8][8];
    #pragma unroll
    for (int i = 0; i < 8; i++)
        #pragma unroll
        for (int j = 0; j < 8; j++) acc[i][j] = 0.f;

    for (int k0 = 0; k0 < K; k0 += 8) {
        As[lk+0][lrow] = av.x; As[lk+1][lrow] = av.y;
        As[lk+2][lrow] = av.z; As[lk+3][lrow] = av.w;
        Bs[lk+0][lrow] = wv.x; Bs[lk+1][lrow] = wv.y;
        Bs[lk+2][lrow] = wv.z; Bs[lk+3][lrow] = wv.w;
        __syncthreads();

        if (k0 + 8 < K) {
            av = *(const float4*)(Ap + k0 + 8);
            wv = *(const float4*)(Wp + k0 + 8);
        }

        #pragma unroll
        for (int kk = 0; kk < 8; kk++) {
            float4 a0 = *(const float4*)&As[kk][ty*8];
            float4 a1 = *(const float4*)&As[kk][ty*8+4];
            float4 b0 = *(const float4*)&Bs[kk][tx*8];
            float4 b1 = *(const float4*)&Bs[kk][tx*8+4];
            float a[8] = {a0.x,a0.y,a0.z,a0.w,a1.x,a1.y,a1.z,a1.w};
            float b[8] = {b0.x,b0.y,b0.z,b0.w,b1.x,b1.y,b1.z,b1.w};
            #pragma unroll
            for (int i = 0; i < 8; i++)
                #pragma unroll
                for (int j = 0; j < 8; j++)
                    acc[i][j] = fmaf(a[i], b[j], acc[i][j]);
        }
        __syncthreads();
    }

    float bb[8];
    #pragma unroll
    for (int j = 0; j < 8; j++) bb[j] = bias[n0 + tx*8 + j];

    #pragma unroll
    for (int i = 0; i < 8; i++) {
        float4 r0, r1;
        r0.x = acc[i][0] + bb[0]; r0.y = acc[i][1] + bb[1];
        r0.z = acc[i][2] + bb[2]; r0.w = acc[i][3] + bb[3];
        r1.x = acc[i][4] + bb[4]; r1.y = acc[i][5] + bb[5];
        r1.z = acc[i][6] + bb[6]; r1.w = acc[i][7] + bb[7];
        size_t off = (size_t)(m0 + ty*8 + i) * N + n0 + tx*8;
        *(float4*)&Cm[off]     = r0;
        *(float4*)&Cm[off + 4] = r1;
    }
}

// ---------------------------------------------------------------------------
// RoPE + reshape: qkv[b,t,g,slot,d] -> q[b,g,slot,t,d], k[b,g,t,d], v[b,g,t,d]
// ---------------------------------------------------------------------------
__global__ void rope_kernel(const float* __restrict__ cosb,
                            const float* __restrict__ sinb)
{
    int idx = blockIdx.x * blockDim.x + threadIdx.x;
    const int TOT = Bc * Tc * NGc * 6 * HSc;
    if (idx >= TOT) return;

    int d    = idx % HSc;
    int slot = (idx / HSc) % 6;
    int g    = (idx / (HSc * 6)) % NGc;
    int t    = (idx / (HSc * 6 * NGc)) % Tc;
    int b    = idx / (HSc * 6 * NGc * Tc);

    size_t base = (size_t)(b * Tc + t) * QKVD + (g * 6 + slot) * HSc;
    float x0 = g_qkv[base + d];
    float out;
    if (slot <= QPKc) {  // q slots 0..3 and k slot 4 get RoPE
        float xp = (d < HSc/2) ? -g_qkv[base + d + HSc/2]
                               :  g_qkv[base + d - HSc/2];
        out = x0 * cosb[t * HSc + d] + xp * sinb[t * HSc + d];
    } else {
        out = x0;
    }

    if (slot < QPKc)
        g_q[(((size_t)(b * NGc + g) * QPKc + slot) * Tc + t) * HSc + d] = out;
    else if (slot == QPKc)
        g_k[((size_t)(b * NGc + g) * Tc + t) * HSc + d] = out;
    else
        g_v[((size_t)(b * NGc + g) * Tc + t) * HSc + d] = out;
}

// ---------------------------------------------------------------------------
// Flash attention (fp32, causal). 64 query rows per block, 64-key tiles.
// Smem: Qs (q-major), KV (K stored d-major for conflict-free reads; later V
// stored s-major), Ss (P tile). Exactly 48KB static.
// ---------------------------------------------------------------------------
__global__ __launch_bounds__(256) void attn_kernel()
{
    __shared__ float Qs[64][64];
    __shared__ float KV[64][64];
    __shared__ float Ss[64][64];

    const int tid = threadIdx.x;
    const int tx = tid & 15;
    const int ty = tid >> 4;
    const int q0   = blockIdx.x * 64;
    const int slot = blockIdx.y;
    const int bg   = blockIdx.z;            // b*NG + g
    const int b = bg / NGc, g = bg % NGc;

    const float* Q  = g_q + ((size_t)(bg * QPKc + slot) * Tc + q0) * HSc;
    const float* Kp = g_k + (size_t)bg * Tc * HSc;
    const float* Vp = g_v + (size_t)bg * Tc * HSc;

    // Load Q tile (64x64)
    for (int i = tid; i < 64 * 16; i += 256) {
        int r = i >> 4, c4 = (i & 15) << 2;
        *(float4*)&Qs[r][c4] = *(const float4*)(Q + r * HSc + c4);
    }

    float O[4][4];
    #pragma unroll
    for (int i = 0; i < 4; i++)
        #pragma unroll
        for (int j = 0; j < 4; j++) O[i][j] = 0.f;

    float m_i = -INFINITY, l_i = 0.f;   // only meaningful for tid < 64
    const int row = tid;
    const int ntiles = q0 / 64 + 1;
    const float scale = 0.125f;         // 1/sqrt(64)

    for (int st = 0; st < ntiles; st++) {
        const int s0 = st * 64;
        __syncthreads();   // previous V reads done (and Qs load on iter 0)

        // Load K tile transposed: KV[d][c] = K[s0+c][d]
        for (int i = tid; i < 64 * 16; i += 256) {
            int c = i >> 4, d4 = (i & 15) << 2;
            float4 k4 = *(const float4*)(Kp + (size_t)(s0 + c) * HSc + d4);
            KV[d4+0][c] = k4.x; KV[d4+1][c] = k4.y;
            KV[d4+2][c] = k4.z; KV[d4+3][c] = k4.w;
        }
        __syncthreads();

        // S = (Q K^T) * scale  (4x4 per thread)
        float s_acc[4][4];
        #pragma unroll
        for (int i = 0; i < 4; i++)
            #pragma unroll
            for (int j = 0; j < 4; j++) s_acc[i][j] = 0.f;

        #pragma unroll 4
        for (int d = 0; d < 64; d += 4) {
            float a[4][4], bb[4][4];
            #pragma unroll
            for (int i = 0; i < 4; i++) {
                float4 a4 = *(const float4*)&Qs[ty*4 + i][d];
                a[i][0]=a4.x; a[i][1]=a4.y; a[i][2]=a4.z; a[i][3]=a4.w;
            }
            #pragma unroll
            for (int dd = 0; dd < 4; dd++) {
                float4 b4 = *(const float4*)&KV[d + dd][tx*4];
                bb[dd][0]=b4.x; bb[dd][1]=b4.y; bb[dd][2]=b4.z; bb[dd][3]=b4.w;
            }
            #pragma unroll
            for (int i = 0; i < 4; i++)
                #pragma unroll
                for (int j = 0; j < 4; j++)
                    #pragma unroll
                    for (int dd = 0; dd < 4; dd++)
                        s_acc[i][j] = fmaf(a[i][dd], bb[dd][j], s_acc[i][j]);
        }

        // Mask + scale, write to Ss
        #pragma unroll
        for (int i = 0; i < 4; i++) {
            int qrow = q0 + ty*4 + i;
            float4 sv;
            float t0 = s_acc[i][0]*scale, t1 = s_acc[i][1]*scale,
                  t2 = s_acc[i][2]*scale, t3 = s_acc[i][3]*scale;
            int kc = s0 + tx*4;
            sv.x = (kc + 0 > qrow) ? -1e30f : t0;
            sv.y = (kc + 1 > qrow) ? -1e30f : t1;
            sv.z = (kc + 2 > qrow) ? -1e30f : t2;
            sv.w = (kc + 3 > qrow) ? -1e30f : t3;
            *(float4*)&Ss[ty*4 + i][tx*4] = sv;
        }
        __syncthreads();

        // Online softmax row update (tid < 64; rotated scan kills conflicts)
        if (tid < 64) {
            float mx = m_i;
            #pragma unroll 8
            for (int c = 0; c < 64; c++) {
                int cc = (c + row) & 63;
                mx = fmaxf(mx, Ss[row][cc]);
            }
            float al = __expf(m_i - mx);
            float sum = 0.f;
            #pragma unroll 8
            for (int c = 0; c < 64; c++) {
                int cc = (c + row) & 63;
                float p = __expf(Ss[row][cc] - mx);
                Ss[row][cc] = p;
                sum += p;
            }
            l_i = l_i * al + sum;
            m_i = mx;
            KV[0][row] = al;   // stash alpha in dead K storage
        }
        __syncthreads();

        // Rescale O by alpha
        float al4[4];
        #pragma unroll
        for (int i = 0; i < 4; i++) al4[i] = KV[0][ty*4 + i];
        #pragma unroll
        for (int i = 0; i < 4; i++)
            #pragma unroll
            for (int j = 0; j < 4; j++) O[i][j] *= al4[i];
        __syncthreads();   // alpha consumed before V overwrites it

        // Load V tile natural: KV[s][d]
        for (int i = tid; i < 64 * 16; i += 256) {
            int r = i >> 4, d4 = (i & 15) << 2;
            *(float4*)&KV[r][d4] =
                *(const float4*)(Vp + (size_t)(s0 + r) * HSc + d4);
        }
        __syncthreads();

        // O += P @ V
        #pragma unroll 4
        for (int s = 0; s < 64; s += 4) {
            float p[4][4], vv[4][4];
            #pragma unroll
            for (int i = 0; i < 4; i++) {
                float4 p4 = *(const float4*)&Ss[ty*4 + i][s];
                p[i][0]=p4.x; p[i][1]=p4.y; p[i][2]=p4.z; p[i][3]=p4.w;
            }
            #pragma unroll
            for (int ss = 0; ss < 4; ss++) {
                float4 v4 = *(const float4*)&KV[s + ss][tx*4];
                vv[ss][0]=v4.x; vv[ss][1]=v4.y; vv[ss][2]=v4.z; vv[ss][3]=v4.w;
            }
            #pragma unroll
            for (int i = 0; i < 4; i++)
                #pragma unroll
                for (int j = 0; j < 4; j++)
                    #pragma unroll
                    for (int ss = 0; ss < 4; ss++)
                        O[i][j] = fmaf(p[i][ss], vv[ss][j], O[i][j]);
        }
    }

    // Final normalize + write y[b, t, head, d]
    __syncthreads();
    if (tid < 64) KV[0][row] = l_i;
    __syncthreads();

    const int head = g * QPKc + slot;
    #pragma unroll
    for (int i = 0; i < 4; i++) {
        float linv = 1.f / KV[0][ty*4 + i];
        int qrow = q0 + ty*4 + i;
        float4 r;
        r.x = O[i][0]*linv; r.y = O[i][1]*linv;
        r.z = O[i][2]*linv; r.w = O[i][3]*linv;
        size_t off = ((size_t)(b * Tc + qrow) * NHc + head) * HSc + tx*4;
        *(float4*)&g_y[off] = r;
    }
}

// ---------------------------------------------------------------------------
extern "C" void kernel_launch(void* const* d_in, const int* in_sizes, int n_in,
                              void* d_out, int out_size)
{
    const float* x      = (const float*)d_in[0];
    const float* cosb   = (const float*)d_in[1];
    const float* sinb   = (const float*)d_in[2];
    const float* attn_w = (const float*)d_in[3];
    const float* attn_b = (const float*)d_in[4];
    const float* proj_w = (const float*)d_in[5];
    const float* proj_b = (const float*)d_in[6];
    float* out = (float*)d_out;

    float *qkv_p, *y_p;
    cudaGetSymbolAddress((void**)&qkv_p, g_qkv);
    cudaGetSymbolAddress((void**)&y_p,   g_y);

    // 1. QKV GEMM: [4096,3072] = x[4096,2048] @ attn_w[3072,2048]^T + b
    gemm_nt<<<dim3(QKVD/128, BTc/128), 256>>>(x, attn_w, attn_b, qkv_p,
                                              BTc, QKVD, Cc);

    // 2. RoPE + reshape
    {
        int tot = Bc * Tc * NGc * 6 * HSc;
        rope_kernel<<<(tot + 255) / 256, 256>>>(cosb, sinb);
    }

    // 3. Flash attention
    attn_kernel<<<dim3(Tc/64, QPKc, Bc*NGc), 256>>>();

    // 4. Output projection: out[4096,2048] = y @ proj_w[2048,2048]^T + b
    gemm_nt<<<dim3(Cc/128, BTc/128), 256>>>(y_p, proj_w, proj_b, out,
                                            BTc, Cc, Cc);
}

// round 2
// speedup vs baseline: 3.7273x; 3.7273x over previous
#include <cuda_runtime.h>
#include <math.h>
#include <stdint.h>

// Problem constants
#define Bc    2
#define Tc    2048
#define Cc    2048
#define NHc   32
#define NGc   8
#define QPKc  4
#define HSc   64
#define QKVD  3072          // (32 + 2*8) * 64
#define BTc   (Bc*Tc)       // 4096

// Scratch (device globals: allocation-free)
__device__ float g_qkv[(size_t)BTc * QKVD];
__device__ float g_q[(size_t)Bc * NGc * QPKc * Tc * HSc];
__device__ float g_k[(size_t)Bc * NGc * Tc * HSc];
__device__ float g_v[(size_t)Bc * NGc * Tc * HSc];
__device__ float g_y[(size_t)BTc * Cc];

// ---------------------------------------------------------------------------
// tf32 helpers
// ---------------------------------------------------------------------------
__device__ __forceinline__ float f2tff(float f) {
    unsigned u;
    asm("cvt.rna.tf32.f32 %0, %1;" : "=r"(u) : "f"(f));
    return __uint_as_float(u);
}

__device__ __forceinline__ void mma8(float* c, const unsigned* a, const unsigned* b) {
    asm volatile(
        "mma.sync.aligned.m16n8k8.row.col.f32.tf32.tf32.f32 "
        "{%0,%1,%2,%3}, {%4,%5,%6,%7}, {%8,%9}, {%0,%1,%2,%3};\n"
        : "+f"(c[0]), "+f"(c[1]), "+f"(c[2]), "+f"(c[3])
        : "r"(a[0]), "r"(a[1]), "r"(a[2]), "r"(a[3]), "r"(b[0]), "r"(b[1]));
}

// ---------------------------------------------------------------------------
// GEMM (NT) with tf32 tensor cores: C[M,N] = A[M,K] @ W[N,K]^T + bias[N]
// 128x128 tile, BK=16, 256 threads (8 warps of 64x32), k-permuted smem so
// every fragment load is a conflict-free float2.
// ---------------------------------------------------------------------------
#define GP 24   // smem row pitch (16 k + 8 pad)

__global__ __launch_bounds__(256, 2) void gemm_tf32(
    const float* __restrict__ A, const float* __restrict__ W,
    const float* __restrict__ bias, float* __restrict__ Cm,
    int M, int N, int K)
{
    __shared__ float As[128 * GP];
    __shared__ float Ws[128 * GP];

    const int tid  = threadIdx.x;
    const int lane = tid & 31;
    const int warp = tid >> 5;
    const int wm = warp >> 2;        // 0..1
    const int wn = warp & 3;         // 0..3
    const int qr = lane >> 2;        // 0..7
    const int qc = lane & 3;         // 0..3

    const int m0 = blockIdx.y << 7;
    const int n0 = blockIdx.x << 7;

    // loader mapping: 64 rows x 4 float4, each thread handles rows lr, lr+64
    const int lr = tid >> 2;             // 0..63
    const int kq = (tid & 3) << 2;       // 0,4,8,12 (logical k base)
    const int pbase = ((kq >> 3) << 3) | ((kq >> 2) & 1);  // permuted col base

    const float* Ap0 = A + (size_t)(m0 + lr) * K + kq;
    const float* Ap1 = A + (size_t)(m0 + lr + 64) * K + kq;
    const float* Wp0 = W + (size_t)(n0 + lr) * K + kq;
    const float* Wp1 = W + (size_t)(n0 + lr + 64) * K + kq;

    float4 a0v = *(const float4*)Ap0;
    float4 a1v = *(const float4*)Ap1;
    float4 w0v = *(const float4*)Wp0;
    float4 w1v = *(const float4*)Wp1;

    float acc[4][4][4];
    #pragma unroll
    for (int i = 0; i < 4; i++)
        #pragma unroll
        for (int j = 0; j < 4; j++)
            #pragma unroll
            for (int c = 0; c < 4; c++) acc[i][j][c] = 0.f;

    for (int k0 = 0; k0 < K; k0 += 16) {
        // store prefetched tiles (tf32-rounded, permuted cols: stride 2)
        {
            int s0 = lr * GP + pbase;
            As[s0 + 0] = f2tff(a0v.x); As[s0 + 2] = f2tff(a0v.y);
            As[s0 + 4] = f2tff(a0v.z); As[s0 + 6] = f2tff(a0v.w);
            int s1 = (lr + 64) * GP + pbase;
            As[s1 + 0] = f2tff(a1v.x); As[s1 + 2] = f2tff(a1v.y);
            As[s1 + 4] = f2tff(a1v.z); As[s1 + 6] = f2tff(a1v.w);
            Ws[s0 + 0] = f2tff(w0v.x); Ws[s0 + 2] = f2tff(w0v.y);
            Ws[s0 + 4] = f2tff(w0v.z); Ws[s0 + 6] = f2tff(w0v.w);
            Ws[s1 + 0] = f2tff(w1v.x); Ws[s1 + 2] = f2tff(w1v.y);
            Ws[s1 + 4] = f2tff(w1v.z); Ws[s1 + 6] = f2tff(w1v.w);
        }
        __syncthreads();

        if (k0 + 16 < K) {
            a0v = *(const float4*)(Ap0 + k0 + 16);
            a1v = *(const float4*)(Ap1 + k0 + 16);
            w0v = *(const float4*)(Wp0 + k0 + 16);
            w1v = *(const float4*)(Wp1 + k0 + 16);
        }

        #pragma unroll
        for (int ks = 0; ks < 2; ks++) {
            unsigned af[4][4], bf[4][2];
            #pragma unroll
            for (int mt = 0; mt < 4; mt++) {
                float2 lo = *(const float2*)&As[(wm*64 + mt*16 + qr)     * GP + ks*8 + 2*qc];
                float2 hi = *(const float2*)&As[(wm*64 + mt*16 + qr + 8) * GP + ks*8 + 2*qc];
                af[mt][0] = __float_as_uint(lo.x);
                af[mt][2] = __float_as_uint(lo.y);
                af[mt][1] = __float_as_uint(hi.x);
                af[mt][3] = __float_as_uint(hi.y);
            }
            #pragma unroll
            for (int nt = 0; nt < 4; nt++) {
                float2 bv = *(const float2*)&Ws[(wn*32 + nt*8 + qr) * GP + ks*8 + 2*qc];
                bf[nt][0] = __float_as_uint(bv.x);
                bf[nt][1] = __float_as_uint(bv.y);
            }
            #pragma unroll
            for (int mt = 0; mt < 4; mt++)
                #pragma unroll
                for (int nt = 0; nt < 4; nt++)
                    mma8(acc[mt][nt], af[mt], bf[nt]);
        }
        __syncthreads();
    }

    // epilogue
    #pragma unroll
    for (int nt = 0; nt < 4; nt++) {
        int col = n0 + wn*32 + nt*8 + 2*qc;
        float2 bia = *(const float2*)&bias[col];
        #pragma unroll
        for (int mt = 0; mt < 4; mt++) {
            int r0 = m0 + wm*64 + mt*16 + qr;
            float2 v0, v1;
            v0.x = acc[mt][nt][0] + bia.x; v0.y = acc[mt][nt][1] + bia.y;
            v1.x = acc[mt][nt][2] + bia.x; v1.y = acc[mt][nt][3] + bia.y;
            *(float2*)&Cm[(size_t)r0 * N + col]       = v0;
            *(float2*)&Cm[(size_t)(r0 + 8) * N + col] = v1;
        }
    }
}

// ---------------------------------------------------------------------------
// RoPE + reshape: qkv[b,t,g,slot,d] -> q[b,g,slot,t,d], k[b,g,t,d], v[b,g,t,d]
// ---------------------------------------------------------------------------
__global__ void rope_kernel(const float* __restrict__ cosb,
                            const float* __restrict__ sinb)
{
    int idx = blockIdx.x * blockDim.x + threadIdx.x;
    const int TOT = Bc * Tc * NGc * 6 * HSc;
    if (idx >= TOT) return;

    int d    = idx % HSc;
    int slot = (idx / HSc) % 6;
    int g    = (idx / (HSc * 6)) % NGc;
    int t    = (idx / (HSc * 6 * NGc)) % Tc;
    int b    = idx / (HSc * 6 * NGc * Tc);

    size_t base = (size_t)(b * Tc + t) * QKVD + (g * 6 + slot) * HSc;
    float x0 = g_qkv[base + d];
    float out;
    if (slot <= QPKc) {
        float xp = (d < HSc/2) ? -g_qkv[base + d + HSc/2]
                               :  g_qkv[base + d - HSc/2];
        out = x0 * cosb[t * HSc + d] + xp * sinb[t * HSc + d];
    } else {
        out = x0;
    }

    if (slot < QPKc)
        g_q[(((size_t)(b * NGc + g) * QPKc + slot) * Tc + t) * HSc + d] = out;
    else if (slot == QPKc)
        g_k[((size_t)(b * NGc + g) * Tc + t) * HSc + d] = out;
    else
        g_v[((size_t)(b * NGc + g) * Tc + t) * HSc + d] = out;
}

// ---------------------------------------------------------------------------
// Flash attention with tf32 mma. 64 q-rows/block, 4 warps (16 rows each),
// 64-key tiles. Register softmax via quad butterfly shuffles. P round-trips
// through smem with the same k-permute so PV fragments are float2 loads.
// ---------------------------------------------------------------------------
#define AP 72   // attention smem pitch

__global__ __launch_bounds__(128) void attn_tf32()
{
    extern __shared__ float sm[];
    float* Qs  = sm;                 // 64 x AP (d-permuted)
    float* KVs = sm + 64 * AP;       // K (d-permuted) then V^T (s-permuted)
    float* Ss  = sm + 2 * 64 * AP;   // P (s-permuted)

    const int tid  = threadIdx.x;
    const int lane = tid & 31;
    const int warp = tid >> 5;       // 0..3
    const int qr = lane >> 2;        // 0..7
    const int qc = lane & 3;         // 0..3

    const int q0   = blockIdx.x << 6;
    const int slot = blockIdx.y;
    const int bg   = blockIdx.z;     // b*NG + g
    const int b = bg >> 3, gg = bg & 7;

    const float* Qp = g_q + ((size_t)(bg * QPKc + slot) * Tc + q0) * HSc;
    const float* Kp = g_k + (size_t)bg * Tc * HSc;
    const float* Vp = g_v + (size_t)bg * Tc * HSc;

    // Load Q tile (d-permuted, tf32-rounded)
    for (int i = tid; i < 64 * 16; i += 128) {
        int r = i >> 4, k4 = (i & 15) << 2;
        float4 q4 = *(const float4*)(Qp + r * HSc + k4);
        int pb = r * AP + (((k4 >> 3) << 3) | ((k4 >> 2) & 1));
        Qs[pb + 0] = f2tff(q4.x); Qs[pb + 2] = f2tff(q4.y);
        Qs[pb + 4] = f2tff(q4.z); Qs[pb + 6] = f2tff(q4.w);
    }

    float co[8][4];
    #pragma unroll
    for (int nt = 0; nt < 8; nt++)
        #pragma unroll
        for (int c = 0; c < 4; c++) co[nt][c] = 0.f;

    float mrow[2] = {-INFINITY, -INFINITY};
    float lrow[2] = {0.f, 0.f};

    const int ntiles = (q0 >> 6) + 1;
    const float scale = 0.125f;
    const int pc0 = 2 * ((2*qc)   & 3) + (((2*qc)   >> 2) & 1);
    const int pc1 = 2 * ((2*qc+1) & 3) + (((2*qc+1) >> 2) & 1);

    for (int st = 0; st < ntiles; st++) {
        const int s0 = st << 6;
        __syncthreads();   // prior PV reads of KVs done; Qs visible

        // Load K tile (d-permuted)
        for (int i = tid; i < 64 * 16; i += 128) {
            int r = i >> 4, k4 = (i & 15) << 2;
            float4 k4v = *(const float4*)(Kp + (size_t)(s0 + r) * HSc + k4);
            int pb = r * AP + (((k4 >> 3) << 3) | ((k4 >> 2) & 1));
            KVs[pb + 0] = f2tff(k4v.x); KVs[pb + 2] = f2tff(k4v.y);
            KVs[pb + 4] = f2tff(k4v.z); KVs[pb + 6] = f2tff(k4v.w);
        }
        __syncthreads();

        // S = Q K^T (tensor core)
        float cs[8][4];
        #pragma unroll
        for (int nt = 0; nt < 8; nt++)
            #pragma unroll
            for (int c = 0; c < 4; c++) cs[nt][c] = 0.f;

        #pragma unroll
        for (int kt = 0; kt < 8; kt++) {
            unsigned af[4];
            float2 lo = *(const float2*)&Qs[(warp*16 + qr)     * AP + kt*8 + 2*qc];
            float2 hi = *(const float2*)&Qs[(warp*16 + qr + 8) * AP + kt*8 + 2*qc];
            af[0] = __float_as_uint(lo.x); af[2] = __float_as_uint(lo.y);
            af[1] = __float_as_uint(hi.x); af[3] = __float_as_uint(hi.y);
            #pragma unroll
            for (int nt = 0; nt < 8; nt++) {
                unsigned bf[2];
                float2 bv = *(const float2*)&KVs[(nt*8 + qr) * AP + kt*8 + 2*qc];
                bf[0] = __float_as_uint(bv.x); bf[1] = __float_as_uint(bv.y);
                mma8(cs[nt], af, bf);
            }
        }

        // scale + causal mask (only the diagonal tile needs masking)
        const bool lastt = (st == ntiles - 1);
        const int r0g = q0 + warp*16 + qr;
        const int r1g = r0g + 8;
        float mx0 = mrow[0], mx1 = mrow[1];
        #pragma unroll
        for (int nt = 0; nt < 8; nt++) {
            int cb = s0 + nt*8 + 2*qc;
            cs[nt][0] *= scale; cs[nt][1] *= scale;
            cs[nt][2] *= scale; cs[nt][3] *= scale;
            if (lastt) {
                if (cb     > r0g) cs[nt][0] = -1e30f;
                if (cb + 1 > r0g) cs[nt][1] = -1e30f;
                if (cb     > r1g) cs[nt][2] = -1e30f;
                if (cb + 1 > r1g) cs[nt][3] = -1e30f;
            }
            mx0 = fmaxf(mx0, fmaxf(cs[nt][0], cs[nt][1]));
            mx1 = fmaxf(mx1, fmaxf(cs[nt][2], cs[nt][3]));
        }
        mx0 = fmaxf(mx0, __shfl_xor_sync(0xffffffffu, mx0, 1));
        mx0 = fmaxf(mx0, __shfl_xor_sync(0xffffffffu, mx0, 2));
        mx1 = fmaxf(mx1, __shfl_xor_sync(0xffffffffu, mx1, 1));
        mx1 = fmaxf(mx1, __shfl_xor_sync(0xffffffffu, mx1, 2));

        float al0 = __expf(mrow[0] - mx0);
        float al1 = __expf(mrow[1] - mx1);
        mrow[0] = mx0; mrow[1] = mx1;

        float sum0 = 0.f, sum1 = 0.f;
        #pragma unroll
        for (int nt = 0; nt < 8; nt++) {
            float p0 = __expf(cs[nt][0] - mx0);
            float p1 = __expf(cs[nt][1] - mx0);
            float p2 = __expf(cs[nt][2] - mx1);
            float p3 = __expf(cs[nt][3] - mx1);
            sum0 += p0 + p1; sum1 += p2 + p3;
            int b0 = (warp*16 + qr)     * AP + nt*8;
            int b1 = (warp*16 + qr + 8) * AP + nt*8;
            Ss[b0 + pc0] = f2tff(p0); Ss[b0 + pc1] = f2tff(p1);
            Ss[b1 + pc0] = f2tff(p2); Ss[b1 + pc1] = f2tff(p3);
        }
        sum0 += __shfl_xor_sync(0xffffffffu, sum0, 1);
        sum0 += __shfl_xor_sync(0xffffffffu, sum0, 2);
        sum1 += __shfl_xor_sync(0xffffffffu, sum1, 1);
        sum1 += __shfl_xor_sync(0xffffffffu, sum1, 2);
        lrow[0] = lrow[0] * al0 + sum0;
        lrow[1] = lrow[1] * al1 + sum1;

        #pragma unroll
        for (int nt = 0; nt < 8; nt++) {
            co[nt][0] *= al0; co[nt][1] *= al0;
            co[nt][2] *= al1; co[nt][3] *= al1;
        }
        __syncthreads();   // all warps done reading K; Ss fully written

        // Load V transposed (V^T[d][s], s-permuted)
        for (int i = tid; i < 64 * 16; i += 128) {
            int s = i >> 4, d4 = (i & 15) << 2;
            float4 v4 = *(const float4*)(Vp + (size_t)(s0 + s) * HSc + d4);
            int ps = ((s >> 3) << 3) | (2 * (s & 3)) | ((s >> 2) & 1);
            KVs[(d4 + 0) * AP + ps] = f2tff(v4.x);
            KVs[(d4 + 1) * AP + ps] = f2tff(v4.y);
            KVs[(d4 + 2) * AP + ps] = f2tff(v4.z);
            KVs[(d4 + 3) * AP + ps] = f2tff(v4.w);
        }
        __syncthreads();

        // O += P V (tensor core)
        #pragma unroll
        for (int kt = 0; kt < 8; kt++) {
            unsigned af[4];
            float2 lo = *(const float2*)&Ss[(warp*16 + qr)     * AP + kt*8 + 2*qc];
            float2 hi = *(const float2*)&Ss[(warp*16 + qr + 8) * AP + kt*8 + 2*qc];
            af[0] = __float_as_uint(lo.x); af[2] = __float_as_uint(lo.y);
            af[1] = __float_as_uint(hi.x); af[3] = __float_as_uint(hi.y);
            #pragma unroll
            for (int nt = 0; nt < 8; nt++) {
                unsigned bf[2];
                float2 bv = *(const float2*)&KVs[(nt*8 + qr) * AP + kt*8 + 2*qc];
                bf[0] = __float_as_uint(bv.x); bf[1] = __float_as_uint(bv.y);
                mma8(co[nt], af, bf);
            }
        }
    }

    // Normalize + write y[b, t, head, d]
    const float il0 = 1.f / lrow[0];
    const float il1 = 1.f / lrow[1];
    const int head = gg * QPKc + slot;
    const int r0g = q0 + warp*16 + qr;
    #pragma unroll
    for (int nt = 0; nt < 8; nt++) {
        int d = nt*8 + 2*qc;
        float2 v0, v1;
        v0.x = co[nt][0] * il0; v0.y = co[nt][1] * il0;
        v1.x = co[nt][2] * il1; v1.y = co[nt][3] * il1;
        *(float2*)&g_y[((size_t)(b * Tc + r0g)     * NHc + head) * HSc + d] = v0;
        *(float2*)&g_y[((size_t)(b * Tc + r0g + 8) * NHc + head) * HSc + d] = v1;
    }
}

// ---------------------------------------------------------------------------
extern "C" void kernel_launch(void* const* d_in, const int* in_sizes, int n_in,
                              void* d_out, int out_size)
{
    const float* x      = (const float*)d_in[0];
    const float* cosb   = (const float*)d_in[1];
    const float* sinb   = (const float*)d_in[2];
    const float* attn_w = (const float*)d_in[3];
    const float* attn_b = (const float*)d_in[4];
    const float* proj_w = (const float*)d_in[5];
    const float* proj_b = (const float*)d_in[6];
    float* out = (float*)d_out;

    float *qkv_p, *y_p;
    cudaGetSymbolAddress((void**)&qkv_p, g_qkv);
    cudaGetSymbolAddress((void**)&y_p,   g_y);

    const int attn_smem = 3 * 64 * AP * sizeof(float);   // 55296 B
    cudaFuncSetAttribute(attn_tf32,
                         cudaFuncAttributeMaxDynamicSharedMemorySize, attn_smem);

    // 1. QKV GEMM: [4096,3072] = x[4096,2048] @ attn_w[3072,2048]^T + b
    gemm_tf32<<<dim3(QKVD/128, BTc/128), 256>>>(x, attn_w, attn_b, qkv_p,
                                                BTc, QKVD, Cc);

    // 2. RoPE + reshape
    {
        int tot = Bc * Tc * NGc * 6 * HSc;
        rope_kernel<<<(tot + 255) / 256, 256>>>(cosb, sinb);
    }

    // 3. Flash attention (tf32 tensor cores)
    attn_tf32<<<dim3(Tc/64, QPKc, Bc*NGc), 128, attn_smem>>>();

    // 4. Output projection: out[4096,2048] = y @ proj_w[2048,2048]^T + b
    gemm_tf32<<<dim3(Cc/128, BTc/128), 256>>>(y_p, proj_w, proj_b, out,
                                              BTc, Cc, Cc);
}

// round 4
// speedup vs baseline: 5.2548x; 1.4098x over previous
#include <cuda_runtime.h>
#include <cuda_fp16.h>
#include <math.h>
#include <stdint.h>

// Problem constants
#define Bc    2
#define Tc    2048
#define Cc    2048
#define NHc   32
#define NGc   8
#define QPKc  4
#define HSc   64
#define QKVD  3072
#define BTc   (Bc*Tc)       // 4096

// Scratch (device globals: allocation-free)
__device__ float g_qkv[(size_t)BTc * QKVD];
__device__ float g_y[(size_t)BTc * Cc];
__device__ __half g_qh[(size_t)Bc * NGc * QPKc * Tc * HSc];  // fp16, pre-scaled
__device__ __half g_kh[(size_t)Bc * NGc * Tc * HSc];         // fp16 [s][d]
__device__ __half g_vt[(size_t)Bc * NGc * HSc * Tc];         // fp16 transposed [d][t]

// ---------------------------------------------------------------------------
// tf32 helpers (GEMM path, proven in R2)
// ---------------------------------------------------------------------------
__device__ __forceinline__ float f2tff(float f) {
    unsigned u;
    asm("cvt.rna.tf32.f32 %0, %1;" : "=r"(u) : "f"(f));
    return __uint_as_float(u);
}
__device__ __forceinline__ void mma8(float* c, const unsigned* a, const unsigned* b) {
    asm volatile(
        "mma.sync.aligned.m16n8k8.row.col.f32.tf32.tf32.f32 "
        "{%0,%1,%2,%3}, {%4,%5,%6,%7}, {%8,%9}, {%0,%1,%2,%3};\n"
        : "+f"(c[0]), "+f"(c[1]), "+f"(c[2]), "+f"(c[3])
        : "r"(a[0]), "r"(a[1]), "r"(a[2]), "r"(a[3]), "r"(b[0]), "r"(b[1]));
}
// fp16 mma m16n8k16
__device__ __forceinline__ void mma16(float* c, const uint32_t* a,
                                      uint32_t b0, uint32_t b1) {
    asm volatile(
        "mma.sync.aligned.m16n8k16.row.col.f32.f16.f16.f32 "
        "{%0,%1,%2,%3}, {%4,%5,%6,%7}, {%8,%9}, {%0,%1,%2,%3};\n"
        : "+f"(c[0]), "+f"(c[1]), "+f"(c[2]), "+f"(c[3])
        : "r"(a[0]), "r"(a[1]), "r"(a[2]), "r"(a[3]), "r"(b0), "r"(b1));
}
__device__ __forceinline__ uint32_t packh2(float x, float y) {
    __half2 h = __floats2half2_rn(x, y);
    return *(uint32_t*)&h;
}

// ---------------------------------------------------------------------------
// GEMM (NT) tf32: C[M,N] = A[M,K] @ W[N,K]^T + bias[N]   (R2, proven)
// ---------------------------------------------------------------------------
#define GP 24

__global__ __launch_bounds__(256, 2) void gemm_tf32(
    const float* __restrict__ A, const float* __restrict__ W,
    const float* __restrict__ bias, float* __restrict__ Cm,
    int M, int N, int K)
{
    __shared__ float As[128 * GP];
    __shared__ float Ws[128 * GP];

    const int tid  = threadIdx.x;
    const int lane = tid & 31;
    const int warp = tid >> 5;
    const int wm = warp >> 2;
    const int wn = warp & 3;
    const int qr = lane >> 2;
    const int qc = lane & 3;

    const int m0 = blockIdx.y << 7;
    const int n0 = blockIdx.x << 7;

    const int lr = tid >> 2;
    const int kq = (tid & 3) << 2;
    const int pbase = ((kq >> 3) << 3) | ((kq >> 2) & 1);

    const float* Ap0 = A + (size_t)(m0 + lr) * K + kq;
    const float* Ap1 = A + (size_t)(m0 + lr + 64) * K + kq;
    const float* Wp0 = W + (size_t)(n0 + lr) * K + kq;
    const float* Wp1 = W + (size_t)(n0 + lr + 64) * K + kq;

    float4 a0v = *(const float4*)Ap0;
    float4 a1v = *(const float4*)Ap1;
    float4 w0v = *(const float4*)Wp0;
    float4 w1v = *(const float4*)Wp1;

    float acc[4][4][4];
    #pragma unroll
    for (int i = 0; i < 4; i++)
        #pragma unroll
        for (int j = 0; j < 4; j++)
            #pragma unroll
            for (int c = 0; c < 4; c++) acc[i][j][c] = 0.f;

    for (int k0 = 0; k0 < K; k0 += 16) {
        {
            int s0 = lr * GP + pbase;
            As[s0 + 0] = f2tff(a0v.x); As[s0 + 2] = f2tff(a0v.y);
            As[s0 + 4] = f2tff(a0v.z); As[s0 + 6] = f2tff(a0v.w);
            int s1 = (lr + 64) * GP + pbase;
            As[s1 + 0] = f2tff(a1v.x); As[s1 + 2] = f2tff(a1v.y);
            As[s1 + 4] = f2tff(a1v.z); As[s1 + 6] = f2tff(a1v.w);
            Ws[s0 + 0] = f2tff(w0v.x); Ws[s0 + 2] = f2tff(w0v.y);
            Ws[s0 + 4] = f2tff(w0v.z); Ws[s0 + 6] = f2tff(w0v.w);
            Ws[s1 + 0] = f2tff(w1v.x); Ws[s1 + 2] = f2tff(w1v.y);
            Ws[s1 + 4] = f2tff(w1v.z); Ws[s1 + 6] = f2tff(w1v.w);
        }
        __syncthreads();

        if (k0 + 16 < K) {
            a0v = *(const float4*)(Ap0 + k0 + 16);
            a1v = *(const float4*)(Ap1 + k0 + 16);
            w0v = *(const float4*)(Wp0 + k0 + 16);
            w1v = *(const float4*)(Wp1 + k0 + 16);
        }

        #pragma unroll
        for (int ks = 0; ks < 2; ks++) {
            unsigned af[4][4], bf[4][2];
            #pragma unroll
            for (int mt = 0; mt < 4; mt++) {
                float2 lo = *(const float2*)&As[(wm*64 + mt*16 + qr)     * GP + ks*8 + 2*qc];
                float2 hi = *(const float2*)&As[(wm*64 + mt*16 + qr + 8) * GP + ks*8 + 2*qc];
                af[mt][0] = __float_as_uint(lo.x);
                af[mt][2] = __float_as_uint(lo.y);
                af[mt][1] = __float_as_uint(hi.x);
                af[mt][3] = __float_as_uint(hi.y);
            }
            #pragma unroll
            for (int nt = 0; nt < 4; nt++) {
                float2 bv = *(const float2*)&Ws[(wn*32 + nt*8 + qr) * GP + ks*8 + 2*qc];
                bf[nt][0] = __float_as_uint(bv.x);
                bf[nt][1] = __float_as_uint(bv.y);
            }
            #pragma unroll
            for (int mt = 0; mt < 4; mt++)
                #pragma unroll
                for (int nt = 0; nt < 4; nt++)
                    mma8(acc[mt][nt], af[mt], bf[nt]);
        }
        __syncthreads();
    }

    #pragma unroll
    for (int nt = 0; nt < 4; nt++) {
        int col = n0 + wn*32 + nt*8 + 2*qc;
        float2 bia = *(const float2*)&bias[col];
        #pragma unroll
        for (int mt = 0; mt < 4; mt++) {
            int r0 = m0 + wm*64 + mt*16 + qr;
            float2 v0, v1;
            v0.x = acc[mt][nt][0] + bia.x; v0.y = acc[mt][nt][1] + bia.y;
            v1.x = acc[mt][nt][2] + bia.x; v1.y = acc[mt][nt][3] + bia.y;
            *(float2*)&Cm[(size_t)r0 * N + col]       = v0;
            *(float2*)&Cm[(size_t)(r0 + 8) * N + col] = v1;
        }
    }
}

// ---------------------------------------------------------------------------
// RoPE + reshape + fp16 convert.
// q -> g_qh (scaled by 0.125*log2e), k -> g_kh, v -> g_vt (transposed [d][t])
// ---------------------------------------------------------------------------
#define QSCALE (0.125f * 1.44269504088896f)

__global__ void rope_kernel(const float* __restrict__ cosb,
                            const float* __restrict__ sinb)
{
    int idx = blockIdx.x * blockDim.x + threadIdx.x;
    const int TOT = Bc * Tc * NGc * 6 * HSc;
    if (idx >= TOT) return;

    int d    = idx % HSc;
    int slot = (idx / HSc) % 6;
    int g    = (idx / (HSc * 6)) % NGc;
    int t    = (idx / (HSc * 6 * NGc)) % Tc;
    int b    = idx / (HSc * 6 * NGc * Tc);
    int bg   = b * NGc + g;

    size_t base = (size_t)(b * Tc + t) * QKVD + (g * 6 + slot) * HSc;
    float x0 = g_qkv[base + d];
    float out;
    if (slot <= QPKc) {
        float xp = (d < HSc/2) ? -g_qkv[base + d + HSc/2]
                               :  g_qkv[base + d - HSc/2];
        out = x0 * cosb[t * HSc + d] + xp * sinb[t * HSc + d];
    } else {
        out = x0;
    }

    if (slot < QPKc)
        g_qh[(((size_t)(bg * QPKc + slot)) * Tc + t) * HSc + d] =
            __float2half(out * QSCALE);
    else if (slot == QPKc)
        g_kh[((size_t)bg * Tc + t) * HSc + d] = __float2half(out);
    else
        g_vt[((size_t)bg * HSc + d) * Tc + t] = __float2half(out);
}

// ---------------------------------------------------------------------------
// Flash attention, fp16 HMMA (m16n8k16). 64 q-rows/block, 4 warps.
// Smem: u32 pair-arrays, pitch 36 words -> all fragment LDS conflict-free.
// P stays in registers (C-frag == A-frag layout for f16 k16).
// ---------------------------------------------------------------------------
#define PW 36

__global__ __launch_bounds__(128) void attn_h()
{
    __shared__ uint32_t Qs[64 * PW];
    __shared__ uint32_t Ks[64 * PW];
    __shared__ uint32_t Vt[64 * PW];

    const int tid  = threadIdx.x;
    const int lane = tid & 31;
    const int warp = tid >> 5;
    const int qr = lane >> 2;
    const int qc = lane & 3;

    const int q0   = blockIdx.x << 6;
    const int slot = blockIdx.y;
    const int bg   = blockIdx.z;
    const int b = bg >> 3, gg = bg & 7;

    const __half* Qp = g_qh + ((size_t)(bg * QPKc + slot) * Tc + q0) * HSc;
    const __half* Kp = g_kh + (size_t)bg * Tc * HSc;
    const __half* Vp = g_vt + (size_t)bg * HSc * Tc;   // [d][t]

    // Load Q tile: rows t (64), 8 fp16 per uint4 -> 4 u32 words
    {
        const int r = tid >> 3, c = tid & 7;      // 16 rows per pass? 128 thr: r 0..15
        #pragma unroll
        for (int j = 0; j < 4; j++) {
            int rr = r + 16 * j;
            uint4 v = *(const uint4*)(Qp + rr * HSc + c * 8);
            *(uint4*)&Qs[rr * PW + c * 4] = v;
        }
    }

    float co[8][4];
    #pragma unroll
    for (int nt = 0; nt < 8; nt++)
        #pragma unroll
        for (int c = 0; c < 4; c++) co[nt][c] = 0.f;

    float mrow[2] = {-INFINITY, -INFINITY};
    float lrow[2] = {0.f, 0.f};

    const int ntiles = (q0 >> 6) + 1;

    for (int st = 0; st < ntiles; st++) {
        const int s0 = st << 6;
        __syncthreads();   // previous tile's fragment reads complete

        // Load K tile [s][d-pairs]
        {
            const int r = tid >> 3, c = tid & 7;
            #pragma unroll
            for (int j = 0; j < 4; j++) {
                int rr = r + 16 * j;
                uint4 v = *(const uint4*)(Kp + (size_t)(s0 + rr) * HSc + c * 8);
                *(uint4*)&Ks[rr * PW + c * 4] = v;
            }
        }
        // Load V tile transposed source [d][t]: row d, 8 t per uint4
        {
            const int d = tid >> 1;             // 0..63
            const int c = tid & 1;              // 0..1 -> two uint4 per row half
            #pragma unroll
            for (int j = 0; j < 4; j++) {
                int cc = c + 2 * j;             // 0..7
                uint4 v = *(const uint4*)(Vp + (size_t)d * Tc + s0 + cc * 8);
                *(uint4*)&Vt[d * PW + cc * 4] = v;
            }
        }
        __syncthreads();

        // ---- S = Q K^T (fp16 HMMA, scores in log2 domain: scale pre-folded)
        float cs[8][4];
        #pragma unroll
        for (int nt = 0; nt < 8; nt++)
            #pragma unroll
            for (int c = 0; c < 4; c++) cs[nt][c] = 0.f;

        #pragma unroll
        for (int kt = 0; kt < 4; kt++) {
            uint32_t a[4];
            const int rb = (warp*16 + qr) * PW + kt*8 + qc;
            a[0] = Qs[rb];          a[2] = Qs[rb + 4];
            a[1] = Qs[rb + 8*PW];   a[3] = Qs[rb + 8*PW + 4];
            #pragma unroll
            for (int nt = 0; nt < 8; nt++) {
                const int bb = (nt*8 + qr) * PW + kt*8 + qc;
                mma16(cs[nt], a, Ks[bb], Ks[bb + 4]);
            }
        }

        // ---- mask + online softmax (log2 domain)
        const bool lastt = (st == ntiles - 1);
        const int r0g = q0 + warp*16 + qr;
        const int r1g = r0g + 8;
        float mx0 = mrow[0], mx1 = mrow[1];
        #pragma unroll
        for (int nt = 0; nt < 8; nt++) {
            int cb = s0 + nt*8 + 2*qc;
            if (lastt) {
                if (cb     > r0g) cs[nt][0] = -1e30f;
                if (cb + 1 > r0g) cs[nt][1] = -1e30f;
                if (cb     > r1g) cs[nt][2] = -1e30f;
                if (cb + 1 > r1g) cs[nt][3] = -1e30f;
            }
            mx0 = fmaxf(mx0, fmaxf(cs[nt][0], cs[nt][1]));
            mx1 = fmaxf(mx1, fmaxf(cs[nt][2], cs[nt][3]));
        }
        mx0 = fmaxf(mx0, __shfl_xor_sync(0xffffffffu, mx0, 1));
        mx0 = fmaxf(mx0, __shfl_xor_sync(0xffffffffu, mx0, 2));
        mx1 = fmaxf(mx1, __shfl_xor_sync(0xffffffffu, mx1, 1));
        mx1 = fmaxf(mx1, __shfl_xor_sync(0xffffffffu, mx1, 2));

        float al0 = exp2f(mrow[0] - mx0);
        float al1 = exp2f(mrow[1] - mx1);
        mrow[0] = mx0; mrow[1] = mx1;

        float sum0 = 0.f, sum1 = 0.f;
        #pragma unroll
        for (int nt = 0; nt < 8; nt++) {
            cs[nt][0] = exp2f(cs[nt][0] - mx0);
            cs[nt][1] = exp2f(cs[nt][1] - mx0);
            cs[nt][2] = exp2f(cs[nt][2] - mx1);
            cs[nt][3] = exp2f(cs[nt][3] - mx1);
            sum0 += cs[nt][0] + cs[nt][1];
            sum1 += cs[nt][2] + cs[nt][3];
        }
        sum0 += __shfl_xor_sync(0xffffffffu, sum0, 1);
        sum0 += __shfl_xor_sync(0xffffffffu, sum0, 2);
        sum1 += __shfl_xor_sync(0xffffffffu, sum1, 1);
        sum1 += __shfl_xor_sync(0xffffffffu, sum1, 2);
        lrow[0] = lrow[0] * al0 + sum0;
        lrow[1] = lrow[1] * al1 + sum1;

        #pragma unroll
        for (int nt = 0; nt < 8; nt++) {
            co[nt][0] *= al0; co[nt][1] *= al0;
            co[nt][2] *= al1; co[nt][3] *= al1;
        }

        // ---- O += P V  (P packed from registers; V from Vt smem)
        #pragma unroll
        for (int kt = 0; kt < 4; kt++) {
            uint32_t a[4];
            a[0] = packh2(cs[2*kt][0],   cs[2*kt][1]);
            a[1] = packh2(cs[2*kt][2],   cs[2*kt][3]);
            a[2] = packh2(cs[2*kt+1][0], cs[2*kt+1][1]);
            a[3] = packh2(cs[2*kt+1][2], cs[2*kt+1][3]);
            #pragma unroll
            for (int nt = 0; nt < 8; nt++) {
                const int bb = (nt*8 + qr) * PW + kt*8 + qc;
                mma16(co[nt], a, Vt[bb], Vt[bb + 4]);
            }
        }
    }

    // Normalize + write y[b, t, head, d] fp32
    const float il0 = 1.f / lrow[0];
    const float il1 = 1.f / lrow[1];
    const int head = gg * QPKc + slot;
    const int r0g = q0 + warp*16 + qr;
    #pragma unroll
    for (int nt = 0; nt < 8; nt++) {
        int d = nt*8 + 2*qc;
        float2 v0, v1;
        v0.x = co[nt][0] * il0; v0.y = co[nt][1] * il0;
        v1.x = co[nt][2] * il1; v1.y = co[nt][3] * il1;
        *(float2*)&g_y[((size_t)(b * Tc + r0g)     * NHc + head) * HSc + d] = v0;
        *(float2*)&g_y[((size_t)(b * Tc + r0g + 8) * NHc + head) * HSc + d] = v1;
    }
}

// ---------------------------------------------------------------------------
extern "C" void kernel_launch(void* const* d_in, const int* in_sizes, int n_in,
                              void* d_out, int out_size)
{
    const float* x      = (const float*)d_in[0];
    const float* cosb   = (const float*)d_in[1];
    const float* sinb   = (const float*)d_in[2];
    const float* attn_w = (const float*)d_in[3];
    const float* attn_b = (const float*)d_in[4];
    const float* proj_w = (const float*)d_in[5];
    const float* proj_b = (const float*)d_in[6];
    float* out = (float*)d_out;

    float *qkv_p, *y_p;
    cudaGetSymbolAddress((void**)&qkv_p, g_qkv);
    cudaGetSymbolAddress((void**)&y_p,   g_y);

    // 1. QKV GEMM: [4096,3072] = x[4096,2048] @ attn_w[3072,2048]^T + b
    gemm_tf32<<<dim3(QKVD/128, BTc/128), 256>>>(x, attn_w, attn_b, qkv_p,
                                                BTc, QKVD, Cc);

    // 2. RoPE + reshape + fp16 convert
    {
        int tot = Bc * Tc * NGc * 6 * HSc;
        rope_kernel<<<(tot + 255) / 256, 256>>>(cosb, sinb);
    }

    // 3. Flash attention (fp16 HMMA)
    attn_h<<<dim3(Tc/64, QPKc, Bc*NGc), 128>>>();

    // 4. Output projection: out[4096,2048] = y @ proj_w[2048,2048]^T + b
    gemm_tf32<<<dim3(Cc/128, BTc/128), 256>>>(y_p, proj_w, proj_b, out,
                                              BTc, Cc, Cc);
}

// round 5
// speedup vs baseline: 8.7462x; 1.6644x over previous
#include <cuda_runtime.h>
#include <cuda_fp16.h>
#include <math.h>
#include <stdint.h>

// Problem constants
#define Bc    2
#define Tc    2048
#define Cc    2048
#define NHc   32
#define NGc   8
#define QPKc  4
#define HSc   64
#define QKVD  3072
#define BTc   (Bc*Tc)       // 4096

// Scratch (device globals: allocation-free)
__device__ float  g_qkv[(size_t)BTc * QKVD];
__device__ __half g_xh [(size_t)BTc * Cc];          // x fp16
__device__ __half g_awh[(size_t)QKVD * Cc];         // attn_w fp16
__device__ __half g_pwh[(size_t)Cc * Cc];           // proj_w fp16
__device__ __half g_yh [(size_t)BTc * Cc];          // attention out fp16
__device__ __half g_qh[(size_t)Bc * NGc * QPKc * Tc * HSc];
__device__ __half g_kh[(size_t)Bc * NGc * Tc * HSc];
__device__ __half g_vt[(size_t)Bc * NGc * HSc * Tc];

// ---------------------------------------------------------------------------
// helpers
// ---------------------------------------------------------------------------
__device__ __forceinline__ uint32_t smem_u32(const void* p) {
    uint32_t a;
    asm("{ .reg .u64 t; cvta.to.shared.u64 t, %1; cvt.u32.u64 %0, t; }"
        : "=r"(a) : "l"(p));
    return a;
}
__device__ __forceinline__ void mma16(float* c, const uint32_t* a,
                                      uint32_t b0, uint32_t b1) {
    asm volatile(
        "mma.sync.aligned.m16n8k16.row.col.f32.f16.f16.f32 "
        "{%0,%1,%2,%3}, {%4,%5,%6,%7}, {%8,%9}, {%0,%1,%2,%3};\n"
        : "+f"(c[0]), "+f"(c[1]), "+f"(c[2]), "+f"(c[3])
        : "r"(a[0]), "r"(a[1]), "r"(a[2]), "r"(a[3]), "r"(b0), "r"(b1));
}
__device__ __forceinline__ uint32_t packh2(float x, float y) {
    __half2 h = __floats2half2_rn(x, y);
    return *(uint32_t*)&h;
}
__device__ __forceinline__ void cp_async16(uint32_t saddr, const void* gaddr) {
    asm volatile("cp.async.cg.shared.global [%0], [%1], 16;"
                 :: "r"(saddr), "l"(gaddr));
}
#define CP_COMMIT()  asm volatile("cp.async.commit_group;" ::: "memory")
#define CP_WAIT1()   asm volatile("cp.async.wait_group 1;" ::: "memory")
#define CP_WAIT0()   asm volatile("cp.async.wait_group 0;" ::: "memory")

// ---------------------------------------------------------------------------
// fp32 -> fp16 convert (vectorized, n multiple of 8)
// ---------------------------------------------------------------------------
__global__ void cvt_kernel(const float* __restrict__ src,
                           __half* __restrict__ dst, int n)
{
    int i = (blockIdx.x * blockDim.x + threadIdx.x) << 3;
    if (i >= n) return;
    float4 v0 = *(const float4*)(src + i);
    float4 v1 = *(const float4*)(src + i + 4);
    uint4 o;
    o.x = packh2(v0.x, v0.y); o.y = packh2(v0.z, v0.w);
    o.z = packh2(v1.x, v1.y); o.w = packh2(v1.z, v1.w);
    *(uint4*)&dst[i] = o;
}

// ---------------------------------------------------------------------------
// GEMM (NT) fp16 HMMA: C[M,N] = A[M,K] @ W[N,K]^T + bias[N]
// 128x128 tile, BK=32, 256 threads (8 warps of 64x32), cp.async double buffer.
// Smem pitch 20 words/row -> conflict-free fragment LDS (banks 4*(5r%8)+qc).
// ---------------------------------------------------------------------------
#define GPW 20

__global__ __launch_bounds__(256, 2) void gemm_h(
    const __half* __restrict__ A, const __half* __restrict__ W,
    const float* __restrict__ bias, float* __restrict__ Cm,
    int M, int N, int K)
{
    __shared__ uint32_t As[2][128 * GPW];
    __shared__ uint32_t Ws[2][128 * GPW];

    const int tid  = threadIdx.x;
    const int lane = tid & 31;
    const int warp = tid >> 5;
    const int wm = warp >> 2;        // 0..1
    const int wn = warp & 3;         // 0..3
    const int qr = lane >> 2;        // 0..7
    const int qc = lane & 3;         // 0..3

    const int m0 = blockIdx.y << 7;
    const int n0 = blockIdx.x << 7;

    // loader: row lr (0..127), two 16B chunks lc, lc+1 (of 4 per 32-half row)
    const int lr = tid >> 1;
    const int lc = (tid & 1) << 1;

    const uint32_t sA = smem_u32(As);
    const uint32_t sW = smem_u32(Ws);
    const __half* Ap = A + (size_t)(m0 + lr) * K;
    const __half* Wp = W + (size_t)(n0 + lr) * K;

    float acc[4][4][4];
    #pragma unroll
    for (int i = 0; i < 4; i++)
        #pragma unroll
        for (int j = 0; j < 4; j++)
            #pragma unroll
            for (int c = 0; c < 4; c++) acc[i][j][c] = 0.f;

    const int nsteps = K >> 5;

    // issue stage copies for chunk ks into buffer st
    auto issue = [&](int st, int ks) {
        const int kb = ks << 5;
        #pragma unroll
        for (int j = 0; j < 2; j++) {
            const int c = lc + j;
            const uint32_t so = (uint32_t)((st * 128 * GPW + lr * GPW + c * 4) * 4);
            cp_async16(sA + so, Ap + kb + c * 8);
            cp_async16(sW + so, Wp + kb + c * 8);
        }
        CP_COMMIT();
    };

    issue(0, 0);

    for (int ks = 0; ks < nsteps; ks++) {
        const int st = ks & 1;
        if (ks + 1 < nsteps) { issue(st ^ 1, ks + 1); CP_WAIT1(); }
        else                 { CP_WAIT0(); }
        __syncthreads();

        const uint32_t* AS = As[st];
        const uint32_t* WS = Ws[st];
        #pragma unroll
        for (int kt = 0; kt < 2; kt++) {
            uint32_t af[4][4], bf[4][2];
            #pragma unroll
            for (int mt = 0; mt < 4; mt++) {
                const int rb = (wm*64 + mt*16 + qr) * GPW + kt*8 + qc;
                af[mt][0] = AS[rb];
                af[mt][1] = AS[rb + 8*GPW];
                af[mt][2] = AS[rb + 4];
                af[mt][3] = AS[rb + 8*GPW + 4];
            }
            #pragma unroll
            for (int nt = 0; nt < 4; nt++) {
                const int bb = (wn*32 + nt*8 + qr) * GPW + kt*8 + qc;
                bf[nt][0] = WS[bb];
                bf[nt][1] = WS[bb + 4];
            }
            #pragma unroll
            for (int mt = 0; mt < 4; mt++)
                #pragma unroll
                for (int nt = 0; nt < 4; nt++)
                    mma16(acc[mt][nt], af[mt], bf[nt][0], bf[nt][1]);
        }
        __syncthreads();
    }

    // epilogue (same acc layout as tf32 m16n8k8)
    #pragma unroll
    for (int nt = 0; nt < 4; nt++) {
        int col = n0 + wn*32 + nt*8 + 2*qc;
        float2 bia = *(const float2*)&bias[col];
        #pragma unroll
        for (int mt = 0; mt < 4; mt++) {
            int r0 = m0 + wm*64 + mt*16 + qr;
            float2 v0, v1;
            v0.x = acc[mt][nt][0] + bia.x; v0.y = acc[mt][nt][1] + bia.y;
            v1.x = acc[mt][nt][2] + bia.x; v1.y = acc[mt][nt][3] + bia.y;
            *(float2*)&Cm[(size_t)r0 * N + col]       = v0;
            *(float2*)&Cm[(size_t)(r0 + 8) * N + col] = v1;
        }
    }
}

// ---------------------------------------------------------------------------
// RoPE + reshape + fp16 convert.
// q -> g_qh (scaled by 0.125*log2e), k -> g_kh, v -> g_vt (transposed [d][t])
// ---------------------------------------------------------------------------
#define QSCALE (0.125f * 1.44269504088896f)

__global__ void rope_kernel(const float* __restrict__ cosb,
                            const float* __restrict__ sinb)
{
    int idx = blockIdx.x * blockDim.x + threadIdx.x;
    const int TOT = Bc * Tc * NGc * 6 * HSc;
    if (idx >= TOT) return;

    int d    = idx % HSc;
    int slot = (idx / HSc) % 6;
    int g    = (idx / (HSc * 6)) % NGc;
    int t    = (idx / (HSc * 6 * NGc)) % Tc;
    int b    = idx / (HSc * 6 * NGc * Tc);
    int bg   = b * NGc + g;

    size_t base = (size_t)(b * Tc + t) * QKVD + (g * 6 + slot) * HSc;
    float x0 = g_qkv[base + d];
    float out;
    if (slot <= QPKc) {
        float xp = (d < HSc/2) ? -g_qkv[base + d + HSc/2]
                               :  g_qkv[base + d - HSc/2];
        out = x0 * cosb[t * HSc + d] + xp * sinb[t * HSc + d];
    } else {
        out = x0;
    }

    if (slot < QPKc)
        g_qh[(((size_t)(bg * QPKc + slot)) * Tc + t) * HSc + d] =
            __float2half(out * QSCALE);
    else if (slot == QPKc)
        g_kh[((size_t)bg * Tc + t) * HSc + d] = __float2half(out);
    else
        g_vt[((size_t)bg * HSc + d) * Tc + t] = __float2half(out);
}

// ---------------------------------------------------------------------------
// Flash attention, fp16 HMMA (m16n8k16). 64 q-rows/block, 4 warps. (R4 proven)
// Epilogue writes y as fp16 to g_yh.
// ---------------------------------------------------------------------------
#define PW 36

__global__ __launch_bounds__(128) void attn_h()
{
    __shared__ uint32_t Qs[64 * PW];
    __shared__ uint32_t Ks[64 * PW];
    __shared__ uint32_t Vt[64 * PW];

    const int tid  = threadIdx.x;
    const int lane = tid & 31;
    const int warp = tid >> 5;
    const int qr = lane >> 2;
    const int qc = lane & 3;

    const int q0   = blockIdx.x << 6;
    const int slot = blockIdx.y;
    const int bg   = blockIdx.z;
    const int b = bg >> 3, gg = bg & 7;

    const __half* Qp = g_qh + ((size_t)(bg * QPKc + slot) * Tc + q0) * HSc;
    const __half* Kp = g_kh + (size_t)bg * Tc * HSc;
    const __half* Vp = g_vt + (size_t)bg * HSc * Tc;   // [d][t]

    {
        const int r = tid >> 3, c = tid & 7;
        #pragma unroll
        for (int j = 0; j < 4; j++) {
            int rr = r + 16 * j;
            uint4 v = *(const uint4*)(Qp + rr * HSc + c * 8);
            *(uint4*)&Qs[rr * PW + c * 4] = v;
        }
    }

    float co[8][4];
    #pragma unroll
    for (int nt = 0; nt < 8; nt++)
        #pragma unroll
        for (int c = 0; c < 4; c++) co[nt][c] = 0.f;

    float mrow[2] = {-INFINITY, -INFINITY};
    float lrow[2] = {0.f, 0.f};

    const int ntiles = (q0 >> 6) + 1;

    for (int st = 0; st < ntiles; st++) {
        const int s0 = st << 6;
        __syncthreads();

        {
            const int r = tid >> 3, c = tid & 7;
            #pragma unroll
            for (int j = 0; j < 4; j++) {
                int rr = r + 16 * j;
                uint4 v = *(const uint4*)(Kp + (size_t)(s0 + rr) * HSc + c * 8);
                *(uint4*)&Ks[rr * PW + c * 4] = v;
            }
        }
        {
            const int d = tid >> 1;
            const int c = tid & 1;
            #pragma unroll
            for (int j = 0; j < 4; j++) {
                int cc = c + 2 * j;
                uint4 v = *(const uint4*)(Vp + (size_t)d * Tc + s0 + cc * 8);
                *(uint4*)&Vt[d * PW + cc * 4] = v;
            }
        }
        __syncthreads();

        float cs[8][4];
        #pragma unroll
        for (int nt = 0; nt < 8; nt++)
            #pragma unroll
            for (int c = 0; c < 4; c++) cs[nt][c] = 0.f;

        #pragma unroll
        for (int kt = 0; kt < 4; kt++) {
            uint32_t a[4];
            const int rb = (warp*16 + qr) * PW + kt*8 + qc;
            a[0] = Qs[rb];          a[2] = Qs[rb + 4];
            a[1] = Qs[rb + 8*PW];   a[3] = Qs[rb + 8*PW + 4];
            #pragma unroll
            for (int nt = 0; nt < 8; nt++) {
                const int bb = (nt*8 + qr) * PW + kt*8 + qc;
                mma16(cs[nt], a, Ks[bb], Ks[bb + 4]);
            }
        }

        const bool lastt = (st == ntiles - 1);
        const int r0g = q0 + warp*16 + qr;
        const int r1g = r0g + 8;
        float mx0 = mrow[0], mx1 = mrow[1];
        #pragma unroll
        for (int nt = 0; nt < 8; nt++) {
            int cb = s0 + nt*8 + 2*qc;
            if (lastt) {
                if (cb     > r0g) cs[nt][0] = -1e30f;
                if (cb + 1 > r0g) cs[nt][1] = -1e30f;
                if (cb     > r1g) cs[nt][2] = -1e30f;
                if (cb + 1 > r1g) cs[nt][3] = -1e30f;
            }
            mx0 = fmaxf(mx0, fmaxf(cs[nt][0], cs[nt][1]));
            mx1 = fmaxf(mx1, fmaxf(cs[nt][2], cs[nt][3]));
        }
        mx0 = fmaxf(mx0, __shfl_xor_sync(0xffffffffu, mx0, 1));
        mx0 = fmaxf(mx0, __shfl_xor_sync(0xffffffffu, mx0, 2));
        mx1 = fmaxf(mx1, __shfl_xor_sync(0xffffffffu, mx1, 1));
        mx1 = fmaxf(mx1, __shfl_xor_sync(0xffffffffu, mx1, 2));

        float al0 = exp2f(mrow[0] - mx0);
        float al1 = exp2f(mrow[1] - mx1);
        mrow[0] = mx0; mrow[1] = mx1;

        float sum0 = 0.f, sum1 = 0.f;
        #pragma unroll
        for (int nt = 0; nt < 8; nt++) {
            cs[nt][0] = exp2f(cs[nt][0] - mx0);
            cs[nt][1] = exp2f(cs[nt][1] - mx0);
            cs[nt][2] = exp2f(cs[nt][2] - mx1);
            cs[nt][3] = exp2f(cs[nt][3] - mx1);
            sum0 += cs[nt][0] + cs[nt][1];
            sum1 += cs[nt][2] + cs[nt][3];
        }
        sum0 += __shfl_xor_sync(0xffffffffu, sum0, 1);
        sum0 += __shfl_xor_sync(0xffffffffu, sum0, 2);
        sum1 += __shfl_xor_sync(0xffffffffu, sum1, 1);
        sum1 += __shfl_xor_sync(0xffffffffu, sum1, 2);
        lrow[0] = lrow[0] * al0 + sum0;
        lrow[1] = lrow[1] * al1 + sum1;

        #pragma unroll
        for (int nt = 0; nt < 8; nt++) {
            co[nt][0] *= al0; co[nt][1] *= al0;
            co[nt][2] *= al1; co[nt][3] *= al1;
        }

        #pragma unroll
        for (int kt = 0; kt < 4; kt++) {
            uint32_t a[4];
            a[0] = packh2(cs[2*kt][0],   cs[2*kt][1]);
            a[1] = packh2(cs[2*kt][2],   cs[2*kt][3]);
            a[2] = packh2(cs[2*kt+1][0], cs[2*kt+1][1]);
            a[3] = packh2(cs[2*kt+1][2], cs[2*kt+1][3]);
            #pragma unroll
            for (int nt = 0; nt < 8; nt++) {
                const int bb = (nt*8 + qr) * PW + kt*8 + qc;
                mma16(co[nt], a, Vt[bb], Vt[bb + 4]);
            }
        }
    }

    // Normalize + write y fp16 [b, t, head, d]
    const float il0 = 1.f / lrow[0];
    const float il1 = 1.f / lrow[1];
    const int head = gg * QPKc + slot;
    const int r0g = q0 + warp*16 + qr;
    #pragma unroll
    for (int nt = 0; nt < 8; nt++) {
        int d = nt*8 + 2*qc;
        size_t o0 = ((size_t)(b * Tc + r0g)     * NHc + head) * HSc + d;
        size_t o1 = ((size_t)(b * Tc + r0g + 8) * NHc + head) * HSc + d;
        *(uint32_t*)&g_yh[o0] = packh2(co[nt][0] * il0, co[nt][1] * il0);
        *(uint32_t*)&g_yh[o1] = packh2(co[nt][2] * il1, co[nt][3] * il1);
    }
}

// ---------------------------------------------------------------------------
extern "C" void kernel_launch(void* const* d_in, const int* in_sizes, int n_in,
                              void* d_out, int out_size)
{
    const float* x      = (const float*)d_in[0];
    const float* cosb   = (const float*)d_in[1];
    const float* sinb   = (const float*)d_in[2];
    const float* attn_w = (const float*)d_in[3];
    const float* attn_b = (const float*)d_in[4];
    const float* proj_w = (const float*)d_in[5];
    const float* proj_b = (const float*)d_in[6];
    float* out = (float*)d_out;

    float* qkv_p;
    cudaGetSymbolAddress((void**)&qkv_p, g_qkv);
    __half *xh, *awh, *pwh, *yh;
    cudaGetSymbolAddress((void**)&xh,  g_xh);
    cudaGetSymbolAddress((void**)&awh, g_awh);
    cudaGetSymbolAddress((void**)&pwh, g_pwh);
    cudaGetSymbolAddress((void**)&yh,  g_yh);

    // 0. fp32 -> fp16 converts
    {
        int n;
        n = BTc * Cc;   cvt_kernel<<<n/8/256, 256>>>(x, xh, n);
        n = QKVD * Cc;  cvt_kernel<<<n/8/256, 256>>>(attn_w, awh, n);
        n = Cc * Cc;    cvt_kernel<<<n/8/256, 256>>>(proj_w, pwh, n);
    }

    // 1. QKV GEMM (fp16 HMMA): [4096,3072]
    gemm_h<<<dim3(QKVD/128, BTc/128), 256>>>(xh, awh, attn_b, qkv_p,
                                             BTc, QKVD, Cc);

    // 2. RoPE + reshape + fp16 convert
    {
        int tot = Bc * Tc * NGc * 6 * HSc;
        rope_kernel<<<(tot + 255) / 256, 256>>>(cosb, sinb);
    }

    // 3. Flash attention (fp16 HMMA), writes y fp16
    attn_h<<<dim3(Tc/64, QPKc, Bc*NGc), 128>>>();

    // 4. Output projection (fp16 HMMA): out = y @ proj_w^T + b
    gemm_h<<<dim3(Cc/128, BTc/128), 256>>>(yh, pwh, proj_b, out,
                                           BTc, Cc, Cc);
}

// round 6
// speedup vs baseline: 9.0025x; 1.0293x over previous
#include <cuda_runtime.h>
#include <cuda_fp16.h>
#include <math.h>
#include <stdint.h>

// Problem constants
#define Bc    2
#define Tc    2048
#define Cc    2048
#define NHc   32
#define NGc   8
#define QPKc  4
#define HSc   64
#define QKVD  3072
#define BTc   (Bc*Tc)       // 4096

// Scratch (device globals: allocation-free)
__device__ float  g_qkv[(size_t)BTc * QKVD];
__device__ __half g_xh [(size_t)BTc * Cc];
__device__ __half g_awh[(size_t)QKVD * Cc];
__device__ __half g_pwh[(size_t)Cc * Cc];
__device__ __half g_yh [(size_t)BTc * Cc];
__device__ __half g_qh[(size_t)Bc * NGc * QPKc * Tc * HSc];
__device__ __half g_kh[(size_t)Bc * NGc * Tc * HSc];
__device__ __half g_vt[(size_t)Bc * NGc * HSc * Tc];

// ---------------------------------------------------------------------------
// helpers
// ---------------------------------------------------------------------------
__device__ __forceinline__ uint32_t smem_u32(const void* p) {
    uint32_t a;
    asm("{ .reg .u64 t; cvta.to.shared.u64 t, %1; cvt.u32.u64 %0, t; }"
        : "=r"(a) : "l"(p));
    return a;
}
__device__ __forceinline__ void mma16(float* c, const uint32_t* a,
                                      uint32_t b0, uint32_t b1) {
    asm volatile(
        "mma.sync.aligned.m16n8k16.row.col.f32.f16.f16.f32 "
        "{%0,%1,%2,%3}, {%4,%5,%6,%7}, {%8,%9}, {%0,%1,%2,%3};\n"
        : "+f"(c[0]), "+f"(c[1]), "+f"(c[2]), "+f"(c[3])
        : "r"(a[0]), "r"(a[1]), "r"(a[2]), "r"(a[3]), "r"(b0), "r"(b1));
}
__device__ __forceinline__ uint32_t packh2(float x, float y) {
    __half2 h = __floats2half2_rn(x, y);
    return *(uint32_t*)&h;
}
__device__ __forceinline__ void cp_async16(uint32_t saddr, const void* gaddr) {
    asm volatile("cp.async.cg.shared.global [%0], [%1], 16;"
                 :: "r"(saddr), "l"(gaddr));
}
#define CP_COMMIT()  asm volatile("cp.async.commit_group;" ::: "memory")
#define CP_WAIT1()   asm volatile("cp.async.wait_group 1;" ::: "memory")
#define CP_WAIT0()   asm volatile("cp.async.wait_group 0;" ::: "memory")

// ---------------------------------------------------------------------------
// fp32 -> fp16 convert (vectorized, n multiple of 8)
// ---------------------------------------------------------------------------
__global__ void cvt_kernel(const float* __restrict__ src,
                           __half* __restrict__ dst, int n)
{
    int i = (blockIdx.x * blockDim.x + threadIdx.x) << 3;
    if (i >= n) return;
    float4 v0 = *(const float4*)(src + i);
    float4 v1 = *(const float4*)(src + i + 4);
    uint4 o;
    o.x = packh2(v0.x, v0.y); o.y = packh2(v0.z, v0.w);
    o.z = packh2(v1.x, v1.y); o.w = packh2(v1.z, v1.w);
    *(uint4*)&dst[i] = o;
}

// ---------------------------------------------------------------------------
// GEMM (NT) fp16 HMMA: C = A @ W^T + bias.  128x128 tile, BK=32, 256 thr.
// 3-stage cp.async pipeline, ONE barrier per iteration.
// Smem pitch 20 words/row -> conflict-free fragment LDS.
// ---------------------------------------------------------------------------
#define GPW 20
#define STG_W  (128 * GPW)           // words per array per stage
#define GSMEM  (3 * 2 * STG_W * 4)   // 61440 bytes

__global__ __launch_bounds__(256, 2) void gemm_h(
    const __half* __restrict__ A, const __half* __restrict__ W,
    const float* __restrict__ bias, float* __restrict__ Cm,
    int M, int N, int K)
{
    extern __shared__ uint32_t sh[];

    const int tid  = threadIdx.x;
    const int lane = tid & 31;
    const int warp = tid >> 5;
    const int wm = warp >> 2;
    const int wn = warp & 3;
    const int qr = lane >> 2;
    const int qc = lane & 3;

    const int m0 = blockIdx.y << 7;
    const int n0 = blockIdx.x << 7;

    const int lr = tid >> 1;
    const int lc = (tid & 1) << 1;

    const uint32_t sbase = smem_u32(sh);
    const __half* Ap = A + (size_t)(m0 + lr) * K;
    const __half* Wp = W + (size_t)(n0 + lr) * K;

    float acc[4][4][4];
    #pragma unroll
    for (int i = 0; i < 4; i++)
        #pragma unroll
        for (int j = 0; j < 4; j++)
            #pragma unroll
            for (int c = 0; c < 4; c++) acc[i][j][c] = 0.f;

    const int nsteps = K >> 5;   // 64

    auto issue = [&](int stage, int ks) {
        const int kb = ks << 5;
        const uint32_t so = sbase + (uint32_t)(stage * 2 * STG_W * 4);
        #pragma unroll
        for (int j = 0; j < 2; j++) {
            const int c = lc + j;
            const uint32_t off = (uint32_t)((lr * GPW + c * 4) * 4);
            cp_async16(so + off, Ap + kb + c * 8);
            cp_async16(so + STG_W * 4 + off, Wp + kb + c * 8);
        }
        CP_COMMIT();
    };

    issue(0, 0);
    issue(1, 1);

    int stage = 0;
    for (int ks = 0; ks < nsteps; ks++) {
        if (ks + 1 < nsteps) CP_WAIT1(); else CP_WAIT0();
        __syncthreads();
        if (ks + 2 < nsteps) {
            int ns = stage + 2; if (ns >= 3) ns -= 3;
            issue(ns, ks + 2);
        }

        const uint32_t* AS = sh + stage * 2 * STG_W;
        const uint32_t* WS = AS + STG_W;
        #pragma unroll
        for (int kt = 0; kt < 2; kt++) {
            uint32_t af[4][4], bf[4][2];
            #pragma unroll
            for (int mt = 0; mt < 4; mt++) {
                const int rb = (wm*64 + mt*16 + qr) * GPW + kt*8 + qc;
                af[mt][0] = AS[rb];
                af[mt][1] = AS[rb + 8*GPW];
                af[mt][2] = AS[rb + 4];
                af[mt][3] = AS[rb + 8*GPW + 4];
            }
            #pragma unroll
            for (int nt = 0; nt < 4; nt++) {
                const int bb = (wn*32 + nt*8 + qr) * GPW + kt*8 + qc;
                bf[nt][0] = WS[bb];
                bf[nt][1] = WS[bb + 4];
            }
            #pragma unroll
            for (int mt = 0; mt < 4; mt++)
                #pragma unroll
                for (int nt = 0; nt < 4; nt++)
                    mma16(acc[mt][nt], af[mt], bf[nt][0], bf[nt][1]);
        }
        if (++stage == 3) stage = 0;
    }

    #pragma unroll
    for (int nt = 0; nt < 4; nt++) {
        int col = n0 + wn*32 + nt*8 + 2*qc;
        float2 bia = *(const float2*)&bias[col];
        #pragma unroll
        for (int mt = 0; mt < 4; mt++) {
            int r0 = m0 + wm*64 + mt*16 + qr;
            float2 v0, v1;
            v0.x = acc[mt][nt][0] + bia.x; v0.y = acc[mt][nt][1] + bia.y;
            v1.x = acc[mt][nt][2] + bia.x; v1.y = acc[mt][nt][3] + bia.y;
            *(float2*)&Cm[(size_t)r0 * N + col]       = v0;
            *(float2*)&Cm[(size_t)(r0 + 8) * N + col] = v1;
        }
    }
}

// ---------------------------------------------------------------------------
// RoPE + reshape + fp16 convert.
// ---------------------------------------------------------------------------
#define QSCALE (0.125f * 1.44269504088896f)

__global__ void rope_kernel(const float* __restrict__ cosb,
                            const float* __restrict__ sinb)
{
    int idx = blockIdx.x * blockDim.x + threadIdx.x;
    const int TOT = Bc * Tc * NGc * 6 * HSc;
    if (idx >= TOT) return;

    int d    = idx % HSc;
    int slot = (idx / HSc) % 6;
    int g    = (idx / (HSc * 6)) % NGc;
    int t    = (idx / (HSc * 6 * NGc)) % Tc;
    int b    = idx / (HSc * 6 * NGc * Tc);
    int bg   = b * NGc + g;

    size_t base = (size_t)(b * Tc + t) * QKVD + (g * 6 + slot) * HSc;
    float x0 = g_qkv[base + d];
    float out;
    if (slot <= QPKc) {
        float xp = (d < HSc/2) ? -g_qkv[base + d + HSc/2]
                               :  g_qkv[base + d - HSc/2];
        out = x0 * cosb[t * HSc + d] + xp * sinb[t * HSc + d];
    } else {
        out = x0;
    }

    if (slot < QPKc)
        g_qh[(((size_t)(bg * QPKc + slot)) * Tc + t) * HSc + d] =
            __float2half(out * QSCALE);
    else if (slot == QPKc)
        g_kh[((size_t)bg * Tc + t) * HSc + d] = __float2half(out);
    else
        g_vt[((size_t)bg * HSc + d) * Tc + t] = __float2half(out);
}

// ---------------------------------------------------------------------------
// Flash attention, fp16 HMMA. 128 q-rows/block, 8 warps (16 rows each),
// 64-key tiles shared by all warps. Per-warp inner math identical to R4/R5.
// ---------------------------------------------------------------------------
#define PW 36

__global__ __launch_bounds__(256) void attn_h()
{
    __shared__ uint32_t Qs[128 * PW];
    __shared__ uint32_t Ks[64 * PW];
    __shared__ uint32_t Vt[64 * PW];

    const int tid  = threadIdx.x;
    const int lane = tid & 31;
    const int warp = tid >> 5;     // 0..7
    const int qr = lane >> 2;
    const int qc = lane & 3;

    const int q0   = blockIdx.x << 7;   // 128 q-rows per block
    const int slot = blockIdx.y;
    const int bg   = blockIdx.z;
    const int b = bg >> 3, gg = bg & 7;

    const __half* Qp = g_qh + ((size_t)(bg * QPKc + slot) * Tc + q0) * HSc;
    const __half* Kp = g_kh + (size_t)bg * Tc * HSc;
    const __half* Vp = g_vt + (size_t)bg * HSc * Tc;

    // Load Q tile: 128 rows x 8 uint4
    {
        const int r = tid >> 1, cb = tid & 1;
        #pragma unroll
        for (int j = 0; j < 4; j++) {
            int c = cb + 2 * j;
            uint4 v = *(const uint4*)(Qp + r * HSc + c * 8);
            *(uint4*)&Qs[r * PW + c * 4] = v;
        }
    }

    float co[8][4];
    #pragma unroll
    for (int nt = 0; nt < 8; nt++)
        #pragma unroll
        for (int c = 0; c < 4; c++) co[nt][c] = 0.f;

    float mrow[2] = {-INFINITY, -INFINITY};
    float lrow[2] = {0.f, 0.f};

    const int ntiles = (q0 >> 6) + 2;

    for (int st = 0; st < ntiles; st++) {
        const int s0 = st << 6;
        __syncthreads();

        // K tile: 64 rows x 8 uint4
        {
            const int r = tid >> 2, cb = tid & 3;
            #pragma unroll
            for (int j = 0; j < 2; j++) {
                int c = cb + 4 * j;
                uint4 v = *(const uint4*)(Kp + (size_t)(s0 + r) * HSc + c * 8);
                *(uint4*)&Ks[r * PW + c * 4] = v;
            }
        }
        // V tile (transposed source [d][t]): 64 d-rows x 8 uint4
        {
            const int d = tid >> 2, cb = tid & 3;
            #pragma unroll
            for (int j = 0; j < 2; j++) {
                int c = cb + 4 * j;
                uint4 v = *(const uint4*)(Vp + (size_t)d * Tc + s0 + c * 8);
                *(uint4*)&Vt[d * PW + c * 4] = v;
            }
        }
        __syncthreads();

        // S = Q K^T
        float cs[8][4];
        #pragma unroll
        for (int nt = 0; nt < 8; nt++)
            #pragma unroll
            for (int c = 0; c < 4; c++) cs[nt][c] = 0.f;

        #pragma unroll
        for (int kt = 0; kt < 4; kt++) {
            uint32_t a[4];
            const int rb = (warp*16 + qr) * PW + kt*8 + qc;
            a[0] = Qs[rb];          a[2] = Qs[rb + 4];
            a[1] = Qs[rb + 8*PW];   a[3] = Qs[rb + 8*PW + 4];
            #pragma unroll
            for (int nt = 0; nt < 8; nt++) {
                const int bb = (nt*8 + qr) * PW + kt*8 + qc;
                mma16(cs[nt], a, Ks[bb], Ks[bb + 4]);
            }
        }

        // mask (only last two tiles can cross any diagonal) + online softmax
        const bool maskt = (st >= ntiles - 2);
        const int r0g = q0 + warp*16 + qr;
        const int r1g = r0g + 8;
        float mx0 = mrow[0], mx1 = mrow[1];
        #pragma unroll
        for (int nt = 0; nt < 8; nt++) {
            int cb = s0 + nt*8 + 2*qc;
            if (maskt) {
                if (cb     > r0g) cs[nt][0] = -1e30f;
                if (cb + 1 > r0g) cs[nt][1] = -1e30f;
                if (cb     > r1g) cs[nt][2] = -1e30f;
                if (cb + 1 > r1g) cs[nt][3] = -1e30f;
            }
            mx0 = fmaxf(mx0, fmaxf(cs[nt][0], cs[nt][1]));
            mx1 = fmaxf(mx1, fmaxf(cs[nt][2], cs[nt][3]));
        }
        mx0 = fmaxf(mx0, __shfl_xor_sync(0xffffffffu, mx0, 1));
        mx0 = fmaxf(mx0, __shfl_xor_sync(0xffffffffu, mx0, 2));
        mx1 = fmaxf(mx1, __shfl_xor_sync(0xffffffffu, mx1, 1));
        mx1 = fmaxf(mx1, __shfl_xor_sync(0xffffffffu, mx1, 2));

        float al0 = exp2f(mrow[0] - mx0);
        float al1 = exp2f(mrow[1] - mx1);
        mrow[0] = mx0; mrow[1] = mx1;

        float sum0 = 0.f, sum1 = 0.f;
        #pragma unroll
        for (int nt = 0; nt < 8; nt++) {
            cs[nt][0] = exp2f(cs[nt][0] - mx0);
            cs[nt][1] = exp2f(cs[nt][1] - mx0);
            cs[nt][2] = exp2f(cs[nt][2] - mx1);
            cs[nt][3] = exp2f(cs[nt][3] - mx1);
            sum0 += cs[nt][0] + cs[nt][1];
            sum1 += cs[nt][2] + cs[nt][3];
        }
        sum0 += __shfl_xor_sync(0xffffffffu, sum0, 1);
        sum0 += __shfl_xor_sync(0xffffffffu, sum0, 2);
        sum1 += __shfl_xor_sync(0xffffffffu, sum1, 1);
        sum1 += __shfl_xor_sync(0xffffffffu, sum1, 2);
        lrow[0] = lrow[0] * al0 + sum0;
        lrow[1] = lrow[1] * al1 + sum1;

        #pragma unroll
        for (int nt = 0; nt < 8; nt++) {
            co[nt][0] *= al0; co[nt][1] *= al0;
            co[nt][2] *= al1; co[nt][3] *= al1;
        }

        // O += P V
        #pragma unroll
        for (int kt = 0; kt < 4; kt++) {
            uint32_t a[4];
            a[0] = packh2(cs[2*kt][0],   cs[2*kt][1]);
            a[1] = packh2(cs[2*kt][2],   cs[2*kt][3]);
            a[2] = packh2(cs[2*kt+1][0], cs[2*kt+1][1]);
            a[3] = packh2(cs[2*kt+1][2], cs[2*kt+1][3]);
            #pragma unroll
            for (int nt = 0; nt < 8; nt++) {
                const int bb = (nt*8 + qr) * PW + kt*8 + qc;
                mma16(co[nt], a, Vt[bb], Vt[bb + 4]);
            }
        }
    }

    // Normalize + write y fp16 [b, t, head, d]
    const float il0 = 1.f / lrow[0];
    const float il1 = 1.f / lrow[1];
    const int head = gg * QPKc + slot;
    const int r0g = q0 + warp*16 + qr;
    #pragma unroll
    for (int nt = 0; nt < 8; nt++) {
        int d = nt*8 + 2*qc;
        size_t o0 = ((size_t)(b * Tc + r0g)     * NHc + head) * HSc + d;
        size_t o1 = ((size_t)(b * Tc + r0g + 8) * NHc + head) * HSc + d;
        *(uint32_t*)&g_yh[o0] = packh2(co[nt][0] * il0, co[nt][1] * il0);
        *(uint32_t*)&g_yh[o1] = packh2(co[nt][2] * il1, co[nt][3] * il1);
    }
}

// ---------------------------------------------------------------------------
extern "C" void kernel_launch(void* const* d_in, const int* in_sizes, int n_in,
                              void* d_out, int out_size)
{
    const float* x      = (const float*)d_in[0];
    const float* cosb   = (const float*)d_in[1];
    const float* sinb   = (const float*)d_in[2];
    const float* attn_w = (const float*)d_in[3];
    const float* attn_b = (const float*)d_in[4];
    const float* proj_w = (const float*)d_in[5];
    const float* proj_b = (const float*)d_in[6];
    float* out = (float*)d_out;

    float* qkv_p;
    cudaGetSymbolAddress((void**)&qkv_p, g_qkv);
    __half *xh, *awh, *pwh, *yh;
    cudaGetSymbolAddress((void**)&xh,  g_xh);
    cudaGetSymbolAddress((void**)&awh, g_awh);
    cudaGetSymbolAddress((void**)&pwh, g_pwh);
    cudaGetSymbolAddress((void**)&yh,  g_yh);

    cudaFuncSetAttribute(gemm_h,
                         cudaFuncAttributeMaxDynamicSharedMemorySize, GSMEM);

    // 0. fp32 -> fp16 converts
    {
        int n;
        n = BTc * Cc;   cvt_kernel<<<n/8/256, 256>>>(x, xh, n);
        n = QKVD * Cc;  cvt_kernel<<<n/8/256, 256>>>(attn_w, awh, n);
        n = Cc * Cc;    cvt_kernel<<<n/8/256, 256>>>(proj_w, pwh, n);
    }

    // 1. QKV GEMM
    gemm_h<<<dim3(QKVD/128, BTc/128), 256, GSMEM>>>(xh, awh, attn_b, qkv_p,
                                                    BTc, QKVD, Cc);

    // 2. RoPE + reshape + fp16 convert
    {
        int tot = Bc * Tc * NGc * 6 * HSc;
        rope_kernel<<<(tot + 255) / 256, 256>>>(cosb, sinb);
    }

    // 3. Flash attention (128-row blocks)
    attn_h<<<dim3(Tc/128, QPKc, Bc*NGc), 256>>>();

    // 4. Output projection
    gemm_h<<<dim3(Cc/128, BTc/128), 256, GSMEM>>>(yh, pwh, proj_b, out,
                                                  BTc, Cc, Cc);
}

// round 7
// speedup vs baseline: 9.6619x; 1.0732x over previous
#include <cuda_runtime.h>
#include <cuda_fp16.h>
#include <math.h>
#include <stdint.h>

// Problem constants
#define Bc    2
#define Tc    2048
#define Cc    2048
#define NHc   32
#define NGc   8
#define QPKc  4
#define HSc   64
#define QKVD  3072
#define BTc   (Bc*Tc)       // 4096

// Scratch (device globals: allocation-free)
__device__ __half g_qkv[(size_t)BTc * QKVD];        // fp16 qkv
__device__ __half g_xh [(size_t)BTc * Cc];
__device__ __half g_awh[(size_t)QKVD * Cc];
__device__ __half g_pwh[(size_t)Cc * Cc];
__device__ __half g_yh [(size_t)BTc * Cc];
__device__ __half g_qh[(size_t)Bc * NGc * QPKc * Tc * HSc];
__device__ __half g_kh[(size_t)Bc * NGc * Tc * HSc];
__device__ __half g_vt[(size_t)Bc * NGc * HSc * Tc];

// ---------------------------------------------------------------------------
// helpers
// ---------------------------------------------------------------------------
__device__ __forceinline__ uint32_t smem_u32(const void* p) {
    uint32_t a;
    asm("{ .reg .u64 t; cvta.to.shared.u64 t, %1; cvt.u32.u64 %0, t; }"
        : "=r"(a) : "l"(p));
    return a;
}
__device__ __forceinline__ void mma16(float* c, const uint32_t* a,
                                      uint32_t b0, uint32_t b1) {
    asm volatile(
        "mma.sync.aligned.m16n8k16.row.col.f32.f16.f16.f32 "
        "{%0,%1,%2,%3}, {%4,%5,%6,%7}, {%8,%9}, {%0,%1,%2,%3};\n"
        : "+f"(c[0]), "+f"(c[1]), "+f"(c[2]), "+f"(c[3])
        : "r"(a[0]), "r"(a[1]), "r"(a[2]), "r"(a[3]), "r"(b0), "r"(b1));
}
#define LDSM4(R0,R1,R2,R3,ADDR) \
    asm volatile("ldmatrix.sync.aligned.m8n8.x4.shared.b16 {%0,%1,%2,%3}, [%4];" \
        : "=r"(R0),"=r"(R1),"=r"(R2),"=r"(R3) : "r"(ADDR))

__device__ __forceinline__ uint32_t packh2(float x, float y) {
    __half2 h = __floats2half2_rn(x, y);
    return *(uint32_t*)&h;
}
__device__ __forceinline__ void cp_async16(uint32_t saddr, const void* gaddr) {
    asm volatile("cp.async.cg.shared.global [%0], [%1], 16;"
                 :: "r"(saddr), "l"(gaddr));
}
#define CP_COMMIT()  asm volatile("cp.async.commit_group;" ::: "memory")
#define CP_WAIT1()   asm volatile("cp.async.wait_group 1;" ::: "memory")
#define CP_WAIT0()   asm volatile("cp.async.wait_group 0;" ::: "memory")

// ---------------------------------------------------------------------------
// fp32 -> fp16 convert (vectorized, n multiple of 8)
// ---------------------------------------------------------------------------
__global__ void cvt_kernel(const float* __restrict__ src,
                           __half* __restrict__ dst, int n)
{
    int i = (blockIdx.x * blockDim.x + threadIdx.x) << 3;
    if (i >= n) return;
    float4 v0 = *(const float4*)(src + i);
    float4 v1 = *(const float4*)(src + i + 4);
    uint4 o;
    o.x = packh2(v0.x, v0.y); o.y = packh2(v0.z, v0.w);
    o.z = packh2(v1.x, v1.y); o.w = packh2(v1.z, v1.w);
    *(uint4*)&dst[i] = o;
}

// ---------------------------------------------------------------------------
// GEMM (NT) fp16 HMMA: C = A @ W^T + bias.  128x128 tile, BK=32, 256 thr.
// 3-stage cp.async pipeline, ldmatrix fragment loads. Templated output type.
// ---------------------------------------------------------------------------
#define GPW 20
#define STG_W  (128 * GPW)
#define GSMEM  (3 * 2 * STG_W * 4)   // 61440 bytes

template <typename OT>
__global__ __launch_bounds__(256, 2) void gemm_h(
    const __half* __restrict__ A, const __half* __restrict__ W,
    const float* __restrict__ bias, OT* __restrict__ Cm,
    int M, int N, int K)
{
    extern __shared__ uint32_t sh[];

    const int tid  = threadIdx.x;
    const int lane = tid & 31;
    const int warp = tid >> 5;
    const int wm = warp >> 2;
    const int wn = warp & 3;
    const int qr = lane >> 2;
    const int qc = lane & 3;

    const int m0 = blockIdx.y << 7;
    const int n0 = blockIdx.x << 7;

    const int lr = tid >> 1;
    const int lc = (tid & 1) << 1;

    const uint32_t sbase = smem_u32(sh);
    const __half* Ap = A + (size_t)(m0 + lr) * K;
    const __half* Wp = W + (size_t)(n0 + lr) * K;

    // ldmatrix lane offsets (bytes, within stage region)
    const uint32_t aoff =
        ((wm*64 + ((lane>>3)&1)*8 + (lane&7)) * GPW + (lane>>4)*4) * 4;
    const uint32_t woff =
        ((wn*32 + ((lane>>4)&1)*8 + (lane&7)) * GPW + ((lane>>3)&1)*4) * 4;

    float acc[4][4][4];
    #pragma unroll
    for (int i = 0; i < 4; i++)
        #pragma unroll
        for (int j = 0; j < 4; j++)
            #pragma unroll
            for (int c = 0; c < 4; c++) acc[i][j][c] = 0.f;

    const int nsteps = K >> 5;

    auto issue = [&](int stage, int ks) {
        const int kb = ks << 5;
        const uint32_t so = sbase + (uint32_t)(stage * 2 * STG_W * 4);
        #pragma unroll
        for (int j = 0; j < 2; j++) {
            const int c = lc + j;
            const uint32_t off = (uint32_t)((lr * GPW + c * 4) * 4);
            cp_async16(so + off, Ap + kb + c * 8);
            cp_async16(so + STG_W * 4 + off, Wp + kb + c * 8);
        }
        CP_COMMIT();
    };

    issue(0, 0);
    issue(1, 1);

    int stage = 0;
    for (int ks = 0; ks < nsteps; ks++) {
        if (ks + 1 < nsteps) CP_WAIT1(); else CP_WAIT0();
        __syncthreads();
        if (ks + 2 < nsteps) {
            int ns = stage + 2; if (ns >= 3) ns -= 3;
            issue(ns, ks + 2);
        }

        const uint32_t stb = sbase + (uint32_t)(stage * 2 * STG_W * 4);
        const uint32_t aAddr = stb + aoff;
        const uint32_t wAddr = stb + STG_W * 4 + woff;

        #pragma unroll
        for (int kt = 0; kt < 2; kt++) {
            uint32_t af[4][4], bf[4][2];
            #pragma unroll
            for (int mt = 0; mt < 4; mt++)
                LDSM4(af[mt][0], af[mt][1], af[mt][2], af[mt][3],
                      aAddr + (mt*16*GPW + kt*8) * 4);
            #pragma unroll
            for (int np = 0; np < 2; np++)
                LDSM4(bf[2*np][0], bf[2*np][1], bf[2*np+1][0], bf[2*np+1][1],
                      wAddr + (np*16*GPW + kt*8) * 4);
            #pragma unroll
            for (int mt = 0; mt < 4; mt++)
                #pragma unroll
                for (int nt = 0; nt < 4; nt++)
                    mma16(acc[mt][nt], af[mt], bf[nt][0], bf[nt][1]);
        }
        if (++stage == 3) stage = 0;
    }

    #pragma unroll
    for (int nt = 0; nt < 4; nt++) {
        int col = n0 + wn*32 + nt*8 + 2*qc;
        float2 bia = *(const float2*)&bias[col];
        #pragma unroll
        for (int mt = 0; mt < 4; mt++) {
            int r0 = m0 + wm*64 + mt*16 + qr;
            float v00 = acc[mt][nt][0] + bia.x, v01 = acc[mt][nt][1] + bia.y;
            float v10 = acc[mt][nt][2] + bia.x, v11 = acc[mt][nt][3] + bia.y;
            if (sizeof(OT) == 4) {
                *(float2*)&((float*)Cm)[(size_t)r0 * N + col]       = make_float2(v00, v01);
                *(float2*)&((float*)Cm)[(size_t)(r0 + 8) * N + col] = make_float2(v10, v11);
            } else {
                *(uint32_t*)&((__half*)Cm)[(size_t)r0 * N + col]       = packh2(v00, v01);
                *(uint32_t*)&((__half*)Cm)[(size_t)(r0 + 8) * N + col] = packh2(v10, v11);
            }
        }
    }
}

// ---------------------------------------------------------------------------
// RoPE + reshape (fp16 in, fp16 out).
// ---------------------------------------------------------------------------
#define QSCALE (0.125f * 1.44269504088896f)

__global__ void rope_kernel(const float* __restrict__ cosb,
                            const float* __restrict__ sinb)
{
    int idx = blockIdx.x * blockDim.x + threadIdx.x;
    const int TOT = Bc * Tc * NGc * 6 * HSc;
    if (idx >= TOT) return;

    int d    = idx % HSc;
    int slot = (idx / HSc) % 6;
    int g    = (idx / (HSc * 6)) % NGc;
    int t    = (idx / (HSc * 6 * NGc)) % Tc;
    int b    = idx / (HSc * 6 * NGc * Tc);
    int bg   = b * NGc + g;

    size_t base = (size_t)(b * Tc + t) * QKVD + (g * 6 + slot) * HSc;
    float x0 = __half2float(g_qkv[base + d]);
    float out;
    if (slot <= QPKc) {
        float xp = (d < HSc/2) ? -__half2float(g_qkv[base + d + HSc/2])
                               :  __half2float(g_qkv[base + d - HSc/2]);
        out = x0 * cosb[t * HSc + d] + xp * sinb[t * HSc + d];
    } else {
        out = x0;
    }

    if (slot < QPKc)
        g_qh[(((size_t)(bg * QPKc + slot)) * Tc + t) * HSc + d] =
            __float2half(out * QSCALE);
    else if (slot == QPKc)
        g_kh[((size_t)bg * Tc + t) * HSc + d] = __float2half(out);
    else
        g_vt[((size_t)bg * HSc + d) * Tc + t] = __float2half(out);
}

// ---------------------------------------------------------------------------
// Flash attention, fp16 HMMA + ldmatrix. 128 q-rows/block, 8 warps.
// ---------------------------------------------------------------------------
#define PW 36

__global__ __launch_bounds__(256) void attn_h()
{
    __shared__ uint32_t Qs[128 * PW];
    __shared__ uint32_t Ks[64 * PW];
    __shared__ uint32_t Vt[64 * PW];

    const int tid  = threadIdx.x;
    const int lane = tid & 31;
    const int warp = tid >> 5;
    const int qr = lane >> 2;
    const int qc = lane & 3;

    const int q0   = blockIdx.x << 7;
    const int slot = blockIdx.y;
    const int bg   = blockIdx.z;
    const int b = bg >> 3, gg = bg & 7;

    const __half* Qp = g_qh + ((size_t)(bg * QPKc + slot) * Tc + q0) * HSc;
    const __half* Kp = g_kh + (size_t)bg * Tc * HSc;
    const __half* Vp = g_vt + (size_t)bg * HSc * Tc;

    // ldmatrix lane base addresses
    const uint32_t qAddr = smem_u32(Qs) +
        ((warp*16 + ((lane>>3)&1)*8 + (lane&7)) * PW + (lane>>4)*4) * 4;
    const uint32_t kAddr = smem_u32(Ks) +
        ((((lane>>4)&1)*8 + (lane&7)) * PW + ((lane>>3)&1)*4) * 4;
    const uint32_t vAddr = smem_u32(Vt) +
        ((((lane>>4)&1)*8 + (lane&7)) * PW + ((lane>>3)&1)*4) * 4;

    // Load Q tile: 128 rows x 8 uint4
    {
        const int r = tid >> 1, cb = tid & 1;
        #pragma unroll
        for (int j = 0; j < 4; j++) {
            int c = cb + 2 * j;
            uint4 v = *(const uint4*)(Qp + r * HSc + c * 8);
            *(uint4*)&Qs[r * PW + c * 4] = v;
        }
    }

    float co[8][4];
    #pragma unroll
    for (int nt = 0; nt < 8; nt++)
        #pragma unroll
        for (int c = 0; c < 4; c++) co[nt][c] = 0.f;

    float mrow[2] = {-INFINITY, -INFINITY};
    float lrow[2] = {0.f, 0.f};

    const int ntiles = (q0 >> 6) + 2;

    for (int st = 0; st < ntiles; st++) {
        const int s0 = st << 6;
        __syncthreads();

        {
            const int r = tid >> 2, cb = tid & 3;
            #pragma unroll
            for (int j = 0; j < 2; j++) {
                int c = cb + 4 * j;
                uint4 v = *(const uint4*)(Kp + (size_t)(s0 + r) * HSc + c * 8);
                *(uint4*)&Ks[r * PW + c * 4] = v;
            }
        }
        {
            const int d = tid >> 2, cb = tid & 3;
            #pragma unroll
            for (int j = 0; j < 2; j++) {
                int c = cb + 4 * j;
                uint4 v = *(const uint4*)(Vp + (size_t)d * Tc + s0 + c * 8);
                *(uint4*)&Vt[d * PW + c * 4] = v;
            }
        }
        __syncthreads();

        // S = Q K^T
        float cs[8][4];
        #pragma unroll
        for (int nt = 0; nt < 8; nt++)
            #pragma unroll
            for (int c = 0; c < 4; c++) cs[nt][c] = 0.f;

        #pragma unroll
        for (int kt = 0; kt < 4; kt++) {
            uint32_t a[4];
            LDSM4(a[0], a[1], a[2], a[3], qAddr + kt*32);
            #pragma unroll
            for (int np = 0; np < 4; np++) {
                uint32_t b0, b1, b2, b3;
                LDSM4(b0, b1, b2, b3, kAddr + (np*16*PW + kt*8) * 4);
                mma16(cs[2*np],   a, b0, b1);
                mma16(cs[2*np+1], a, b2, b3);
            }
        }

        // mask + online softmax
        const bool maskt = (st >= ntiles - 2);
        const int r0g = q0 + warp*16 + qr;
        const int r1g = r0g + 8;
        float mx0 = mrow[0], mx1 = mrow[1];
        #pragma unroll
        for (int nt = 0; nt < 8; nt++) {
            int cb = s0 + nt*8 + 2*qc;
            if (maskt) {
                if (cb     > r0g) cs[nt][0] = -1e30f;
                if (cb + 1 > r0g) cs[nt][1] = -1e30f;
                if (cb     > r1g) cs[nt][2] = -1e30f;
                if (cb + 1 > r1g) cs[nt][3] = -1e30f;
            }
            mx0 = fmaxf(mx0, fmaxf(cs[nt][0], cs[nt][1]));
            mx1 = fmaxf(mx1, fmaxf(cs[nt][2], cs[nt][3]));
        }
        mx0 = fmaxf(mx0, __shfl_xor_sync(0xffffffffu, mx0, 1));
        mx0 = fmaxf(mx0, __shfl_xor_sync(0xffffffffu, mx0, 2));
        mx1 = fmaxf(mx1, __shfl_xor_sync(0xffffffffu, mx1, 1));
        mx1 = fmaxf(mx1, __shfl_xor_sync(0xffffffffu, mx1, 2));

        float al0 = exp2f(mrow[0] - mx0);
        float al1 = exp2f(mrow[1] - mx1);
        mrow[0] = mx0; mrow[1] = mx1;

        float sum0 = 0.f, sum1 = 0.f;
        #pragma unroll
        for (int nt = 0; nt < 8; nt++) {
            cs[nt][0] = exp2f(cs[nt][0] - mx0);
            cs[nt][1] = exp2f(cs[nt][1] - mx0);
            cs[nt][2] = exp2f(cs[nt][2] - mx1);
            cs[nt][3] = exp2f(cs[nt][3] - mx1);
            sum0 += cs[nt][0] + cs[nt][1];
            sum1 += cs[nt][2] + cs[nt][3];
        }
        sum0 += __shfl_xor_sync(0xffffffffu, sum0, 1);
        sum0 += __shfl_xor_sync(0xffffffffu, sum0, 2);
        sum1 += __shfl_xor_sync(0xffffffffu, sum1, 1);
        sum1 += __shfl_xor_sync(0xffffffffu, sum1, 2);
        lrow[0] = lrow[0] * al0 + sum0;
        lrow[1] = lrow[1] * al1 + sum1;

        #pragma unroll
        for (int nt = 0; nt < 8; nt++) {
            co[nt][0] *= al0; co[nt][1] *= al0;
            co[nt][2] *= al1; co[nt][3] *= al1;
        }

        // O += P V
        #pragma unroll
        for (int kt = 0; kt < 4; kt++) {
            uint32_t a[4];
            a[0] = packh2(cs[2*kt][0],   cs[2*kt][1]);
            a[1] = packh2(cs[2*kt][2],   cs[2*kt][3]);
            a[2] = packh2(cs[2*kt+1][0], cs[2*kt+1][1]);
            a[3] = packh2(cs[2*kt+1][2], cs[2*kt+1][3]);
            #pragma unroll
            for (int np = 0; np < 4; np++) {
                uint32_t b0, b1, b2, b3;
                LDSM4(b0, b1, b2, b3, vAddr + (np*16*PW + kt*8) * 4);
                mma16(co[2*np],   a, b0, b1);
                mma16(co[2*np+1], a, b2, b3);
            }
        }
    }

    // Normalize + write y fp16 [b, t, head, d]
    const float il0 = 1.f / lrow[0];
    const float il1 = 1.f / lrow[1];
    const int head = gg * QPKc + slot;
    const int r0g = q0 + warp*16 + qr;
    #pragma unroll
    for (int nt = 0; nt < 8; nt++) {
        int d = nt*8 + 2*qc;
        size_t o0 = ((size_t)(b * Tc + r0g)     * NHc + head) * HSc + d;
        size_t o1 = ((size_t)(b * Tc + r0g + 8) * NHc + head) * HSc + d;
        *(uint32_t*)&g_yh[o0] = packh2(co[nt][0] * il0, co[nt][1] * il0);
        *(uint32_t*)&g_yh[o1] = packh2(co[nt][2] * il1, co[nt][3] * il1);
    }
}

// ---------------------------------------------------------------------------
extern "C" void kernel_launch(void* const* d_in, const int* in_sizes, int n_in,
                              void* d_out, int out_size)
{
    const float* x      = (const float*)d_in[0];
    const float* cosb   = (const float*)d_in[1];
    const float* sinb   = (const float*)d_in[2];
    const float* attn_w = (const float*)d_in[3];
    const float* attn_b = (const float*)d_in[4];
    const float* proj_w = (const float*)d_in[5];
    const float* proj_b = (const float*)d_in[6];
    float* out = (float*)d_out;

    __half *qkv_p, *xh, *awh, *pwh, *yh;
    cudaGetSymbolAddress((void**)&qkv_p, g_qkv);
    cudaGetSymbolAddress((void**)&xh,  g_xh);
    cudaGetSymbolAddress((void**)&awh, g_awh);
    cudaGetSymbolAddress((void**)&pwh, g_pwh);
    cudaGetSymbolAddress((void**)&yh,  g_yh);

    cudaFuncSetAttribute(gemm_h<__half>,
                         cudaFuncAttributeMaxDynamicSharedMemorySize, GSMEM);
    cudaFuncSetAttribute(gemm_h<float>,
                         cudaFuncAttributeMaxDynamicSharedMemorySize, GSMEM);

    // 0. fp32 -> fp16 converts
    {
        int n;
        n = BTc * Cc;   cvt_kernel<<<n/8/256, 256>>>(x, xh, n);
        n = QKVD * Cc;  cvt_kernel<<<n/8/256, 256>>>(attn_w, awh, n);
        n = Cc * Cc;    cvt_kernel<<<n/8/256, 256>>>(proj_w, pwh, n);
    }

    // 1. QKV GEMM (fp16 out)
    gemm_h<__half><<<dim3(QKVD/128, BTc/128), 256, GSMEM>>>(
        xh, awh, attn_b, qkv_p, BTc, QKVD, Cc);

    // 2. RoPE + reshape
    {
        int tot = Bc * Tc * NGc * 6 * HSc;
        rope_kernel<<<(tot + 255) / 256, 256>>>(cosb, sinb);
    }

    // 3. Flash attention
    attn_h<<<dim3(Tc/128, QPKc, Bc*NGc), 256>>>();

    // 4. Output projection (fp32 out)
    gemm_h<float><<<dim3(Cc/128, BTc/128), 256, GSMEM>>>(
        yh, pwh, proj_b, out, BTc, Cc, Cc);
}